// round 4
// baseline (speedup 1.0000x reference)
#include <cuda_runtime.h>
#include <math_constants.h>

#define HH   16
#define LL   8192
#define DD   64
#define MB   128
#define NBLK 128
#define TSEL 16

typedef unsigned long long ull;

// scratch (no allocation allowed -> device globals)
__device__ float g_kmean[HH * DD];
__device__ float g_qpool[HH * MB * DD];
__device__ float g_kpool[HH * NBLK * DD];
__device__ int   g_lut[HH * MB * TSEL];

// ---------- f32x2 helpers (Blackwell packed fp32) ----------
static __device__ __forceinline__ ull pk2(float x, float y) {
    ull r;
    asm("mov.b64 %0, {%1, %2};" : "=l"(r) : "f"(x), "f"(y));
    return r;
}
static __device__ __forceinline__ void upk2(ull v, float& x, float& y) {
    asm("mov.b64 {%0, %1}, %2;" : "=f"(x), "=f"(y) : "l"(v));
}
static __device__ __forceinline__ void fma2(ull& d, ull a, ull b) {
    asm("fma.rn.f32x2 %0, %1, %2, %0;" : "+l"(d) : "l"(a), "l"(b));
}
static __device__ __forceinline__ ull mul2(ull a, ull b) {
    ull r;
    asm("mul.rn.f32x2 %0, %1, %2;" : "=l"(r) : "l"(a), "l"(b));
    return r;
}

// ---------- Kernel A: k mean over L per (h, d) ----------
__global__ void kmean_kernel(const float* __restrict__ k) {
    __shared__ float red[512];
    const int h = blockIdx.x;
    const int t = threadIdx.x;
    const int d = t & 63;
    const int g = t >> 6;  // 0..7, each covers 1024 rows
    const float* src = k + ((size_t)h * LL + (size_t)g * 1024) * DD + d;
    float s = 0.f;
#pragma unroll 8
    for (int r = 0; r < 1024; ++r) s += src[(size_t)r * DD];
    red[t] = s;
    __syncthreads();
    if (t < 64) {
        float tot = 0.f;
#pragma unroll
        for (int gg = 0; gg < 8; ++gg) tot += red[t + 64 * gg];
        g_kmean[h * DD + t] = tot * (1.f / 8192.f);
    }
}

// ---------- Kernel B: block pools. z=0 -> q_pool, z=1 -> k_pool (mean-centered) ----------
__global__ void pool_kernel(const float* __restrict__ q, const float* __restrict__ k) {
    const int m = blockIdx.x;
    const int h = blockIdx.y;
    const int d = threadIdx.x;
    const float* base = (blockIdx.z == 0 ? q : k);
    const float* src = base + ((size_t)h * LL + (size_t)m * 64) * DD + d;
    float s = 0.f;
#pragma unroll 8
    for (int r = 0; r < 64; ++r) s += src[r * DD];
    s *= (1.f / 64.f);
    if (blockIdx.z == 0)
        g_qpool[(h * MB + m) * DD + d] = s;
    else
        g_kpool[(h * NBLK + m) * DD + d] = s - g_kmean[h * DD + d];
}

// ---------- Kernel C: block scores + top-16 LUT per (h, m) ----------
__global__ void lut_kernel() {
    __shared__ float qrow[64];
    __shared__ float kp[128 * 65];
    __shared__ float sc[128];
    const int m = blockIdx.x;
    const int h = blockIdx.y;
    const int t = threadIdx.x;

    if (t < 64) qrow[t] = g_qpool[(h * MB + m) * DD + t];
    for (int i = t; i < 128 * 64; i += 128) {
        int n = i >> 6, d = i & 63;
        kp[n * 65 + d] = g_kpool[(h * NBLK + n) * DD + d];
    }
    __syncthreads();

    float acc = 0.f;
#pragma unroll 8
    for (int d = 0; d < 64; ++d) acc += qrow[d] * kp[t * 65 + d];
    sc[t] = acc;
    __syncthreads();

    if (t < 32) {
        for (int r = 0; r < TSEL; ++r) {
            float bv = -CUDART_INF_F;
            int bi = 0;
#pragma unroll
            for (int kk = 0; kk < 4; ++kk) {
                int n = t + 32 * kk;
                float v = sc[n];
                if (v > bv || (v == bv && n < bi)) { bv = v; bi = n; }
            }
#pragma unroll
            for (int s = 16; s > 0; s >>= 1) {
                float ov = __shfl_xor_sync(0xffffffffu, bv, s);
                int   oi = __shfl_xor_sync(0xffffffffu, bi, s);
                if (ov > bv || (ov == bv && oi < bi)) { bv = ov; bi = oi; }
            }
            if (t == 0) {
                g_lut[(h * MB + m) * TSEL + r] = bi;
                sc[bi] = -CUDART_INF_F;
            }
            __syncwarp();
        }
    }
}

// ---------- Kernel D: sparse attention main kernel (v2: un-dup'd smem, register dup) ----------
// smem floats: Qt[64][64] | KT[64][128] | Vs[128][64] | P[64][128] | lut[16]
#define SM_QT 0
#define SM_KT 4096
#define SM_V  12288
#define SM_P  20480
#define SM_LUT 28672
#define SMEM_BYTES ((SM_LUT + 16) * 4)

__global__ void __launch_bounds__(256, 2)
attn_kernel(const float* __restrict__ q, const float* __restrict__ k,
            const float* __restrict__ v, float* __restrict__ out) {
    extern __shared__ float sm[];
    float* Qt = sm + SM_QT;
    float* KT = sm + SM_KT;
    float* Vs = sm + SM_V;
    float* Pm = sm + SM_P;
    int* lut = (int*)(sm + SM_LUT);

    const int m = blockIdx.x;
    const int h = blockIdx.y;
    const int t = threadIdx.x;
    const int tx = t & 7;    // 8 col groups; cols = {ch*32 + 4tx + 0..3 : ch=0..3}
    const int ty = t >> 3;   // 32 row groups (2 rows each)
    const int c = t & 63;    // copy lane: row within a 64-block
    const int dg = t >> 6;   // copy lane: 0..3

    // ---- build Qt[d][r] = q[r][d] * 0.125 (pre-scaled, transposed) ----
    {
        const float* qg = q + ((size_t)h * LL + (size_t)m * 64) * DD;
#pragma unroll
        for (int it = 0; it < 4; ++it) {
            int dc = dg + 4 * it;  // d-quad index 0..15
            float4 qq = *(const float4*)(qg + c * DD + dc * 4);
            Qt[(dc * 4 + 0) * 64 + c] = qq.x * 0.125f;
            Qt[(dc * 4 + 1) * 64 + c] = qq.y * 0.125f;
            Qt[(dc * 4 + 2) * 64 + c] = qq.z * 0.125f;
            Qt[(dc * 4 + 3) * 64 + c] = qq.w * 0.125f;
        }
    }
    if (t < TSEL) lut[t] = g_lut[(h * MB + m) * TSEL + t];

    ull o2[2][4];
    float mrow[2], lrow[2];
#pragma unroll
    for (int i = 0; i < 2; ++i) {
        mrow[i] = -CUDART_INF_F;
        lrow[i] = 0.f;
        o2[i][0] = 0ull; o2[i][1] = 0ull; o2[i][2] = 0ull; o2[i][3] = 0ull;
    }

    const float* kg = k + (size_t)h * LL * DD;
    const float* vg = v + (size_t)h * LL * DD;

    for (int bt = 0; bt < 8; ++bt) {  // 8 iterations x 2 KV blocks
        __syncthreads();
        const int nb0 = lut[2 * bt + 0];
        const int nb1 = lut[2 * bt + 1];

        // ---- load K transposed (both blocks): KT[d][b*64 + c] ----
#pragma unroll
        for (int b = 0; b < 2; ++b) {
            const float* kb = kg + (size_t)(b ? nb1 : nb0) * 64 * DD;
#pragma unroll
            for (int it = 0; it < 4; ++it) {
                int dc = dg + 4 * it;
                float4 kk = *(const float4*)(kb + c * DD + dc * 4);
                KT[(dc * 4 + 0) * 128 + b * 64 + c] = kk.x;
                KT[(dc * 4 + 1) * 128 + b * 64 + c] = kk.y;
                KT[(dc * 4 + 2) * 128 + b * 64 + c] = kk.z;
                KT[(dc * 4 + 3) * 128 + b * 64 + c] = kk.w;
            }
            const float* vb = vg + (size_t)(b ? nb1 : nb0) * 64 * DD;
#pragma unroll
            for (int r = 0; r < 4; ++r) {
                int i4 = t + 256 * r;
                *(float4*)(Vs + b * 4096 + i4 * 4) = *(const float4*)(vb + i4 * 4);
            }
        }
        __syncthreads();

        // ---- S = (Q*scale) @ K^T : per-thread 2 rows x 16 cols (8 f32x2) ----
        ull s2[2][8];
#pragma unroll
        for (int j = 0; j < 8; ++j) { s2[0][j] = 0ull; s2[1][j] = 0ull; }
#pragma unroll 8
        for (int d = 0; d < 64; ++d) {
            ull qll = *(const ull*)(Qt + d * 64 + 2 * ty);
            float qa, qb;
            upk2(qll, qa, qb);
            ull qa2 = pk2(qa, qa);
            ull qb2 = pk2(qb, qb);
#pragma unroll
            for (int ch = 0; ch < 4; ++ch) {
                const ulonglong2 kk = *(const ulonglong2*)(KT + d * 128 + ch * 32 + 4 * tx);
                fma2(s2[0][2 * ch + 0], qa2, kk.x);
                fma2(s2[0][2 * ch + 1], qa2, kk.y);
                fma2(s2[1][2 * ch + 0], qb2, kk.x);
                fma2(s2[1][2 * ch + 1], qb2, kk.y);
            }
        }

        // ---- online softmax per row; stats reduced over the 8-lane tx group ----
#pragma unroll
        for (int i = 0; i < 2; ++i) {
            float vals[16];
#pragma unroll
            for (int j = 0; j < 8; ++j) upk2(s2[i][j], vals[2 * j], vals[2 * j + 1]);
            float mx = vals[0];
#pragma unroll
            for (int j = 1; j < 16; ++j) mx = fmaxf(mx, vals[j]);
#pragma unroll
            for (int s = 4; s > 0; s >>= 1)
                mx = fmaxf(mx, __shfl_xor_sync(0xffffffffu, mx, s));
            float mnew = fmaxf(mrow[i], mx);
            float alpha = __expf(mrow[i] - mnew);
            mrow[i] = mnew;
            float rs = 0.f;
#pragma unroll
            for (int j = 0; j < 16; ++j) {
                vals[j] = __expf(vals[j] - mnew);
                rs += vals[j];
            }
#pragma unroll
            for (int s = 4; s > 0; s >>= 1)
                rs += __shfl_xor_sync(0xffffffffu, rs, s);
            lrow[i] = lrow[i] * alpha + rs;
            ull a2 = pk2(alpha, alpha);
            o2[i][0] = mul2(o2[i][0], a2);
            o2[i][1] = mul2(o2[i][1], a2);
            o2[i][2] = mul2(o2[i][2], a2);
            o2[i][3] = mul2(o2[i][3], a2);
            const int row = 2 * ty + i;
#pragma unroll
            for (int ch = 0; ch < 4; ++ch) {
                *(float4*)(Pm + row * 128 + ch * 32 + 4 * tx) =
                    make_float4(vals[4 * ch + 0], vals[4 * ch + 1],
                                vals[4 * ch + 2], vals[4 * ch + 3]);
            }
        }
        __syncthreads();

        // ---- O += P @ V : per-thread 2 rows x 8 dims ({4tx..+3} and {32+4tx..+3}) ----
#pragma unroll 2
        for (int c0 = 0; c0 < 128; c0 += 4) {
            const float4 p0 = *(const float4*)(Pm + (2 * ty + 0) * 128 + c0);
            const float4 p1 = *(const float4*)(Pm + (2 * ty + 1) * 128 + c0);
            ull pd0[4] = {pk2(p0.x, p0.x), pk2(p0.y, p0.y), pk2(p0.z, p0.z), pk2(p0.w, p0.w)};
            ull pd1[4] = {pk2(p1.x, p1.x), pk2(p1.y, p1.y), pk2(p1.z, p1.z), pk2(p1.w, p1.w)};
#pragma unroll
            for (int j = 0; j < 4; ++j) {
                const float* vr = Vs + (c0 + j) * 64 + 4 * tx;
                const ulonglong2 v0 = *(const ulonglong2*)(vr);
                const ulonglong2 v1 = *(const ulonglong2*)(vr + 32);
                fma2(o2[0][0], pd0[j], v0.x); fma2(o2[0][1], pd0[j], v0.y);
                fma2(o2[0][2], pd0[j], v1.x); fma2(o2[0][3], pd0[j], v1.y);
                fma2(o2[1][0], pd1[j], v0.x); fma2(o2[1][1], pd1[j], v0.y);
                fma2(o2[1][2], pd1[j], v1.x); fma2(o2[1][3], pd1[j], v1.y);
            }
        }
    }

    // ---- normalize + write ----
    float* og = out + ((size_t)h * LL + (size_t)m * 64) * DD;
#pragma unroll
    for (int i = 0; i < 2; ++i) {
        const float inv = 1.0f / lrow[i];
        float a, b, cc, dd2;
        upk2(o2[i][0], a, b);
        upk2(o2[i][1], cc, dd2);
        *(float4*)(og + (2 * ty + i) * DD + 4 * tx) =
            make_float4(a * inv, b * inv, cc * inv, dd2 * inv);
        upk2(o2[i][2], a, b);
        upk2(o2[i][3], cc, dd2);
        *(float4*)(og + (2 * ty + i) * DD + 32 + 4 * tx) =
            make_float4(a * inv, b * inv, cc * inv, dd2 * inv);
    }
}

extern "C" void kernel_launch(void* const* d_in, const int* in_sizes, int n_in,
                              void* d_out, int out_size) {
    const float* q = (const float*)d_in[0];
    const float* k = (const float*)d_in[1];
    const float* v = (const float*)d_in[2];
    float* out = (float*)d_out;

    cudaFuncSetAttribute(attn_kernel, cudaFuncAttributeMaxDynamicSharedMemorySize, SMEM_BYTES);

    kmean_kernel<<<HH, 512>>>(k);
    pool_kernel<<<dim3(MB, HH, 2), 64>>>(q, k);
    lut_kernel<<<dim3(MB, HH), 128>>>();
    attn_kernel<<<dim3(MB, HH), 256, SMEM_BYTES>>>(q, k, v, out);
}

// round 5
// speedup vs baseline: 1.1005x; 1.1005x over previous
#include <cuda_runtime.h>
#include <math_constants.h>

#define HH   16
#define LL   8192
#define DD   64
#define MB   128
#define NBLK 128
#define TSEL 16

typedef unsigned long long ull;

// scratch (no allocation allowed -> device globals)
__device__ float g_kmean[HH * DD];
__device__ float g_qpool[HH * MB * DD];
__device__ float g_kpool[HH * NBLK * DD];
__device__ int   g_lut[HH * MB * TSEL];

// ---------- f32x2 helpers (Blackwell packed fp32) ----------
static __device__ __forceinline__ ull pk2(float x, float y) {
    ull r;
    asm("mov.b64 %0, {%1, %2};" : "=l"(r) : "f"(x), "f"(y));
    return r;
}
static __device__ __forceinline__ void upk2(ull v, float& x, float& y) {
    asm("mov.b64 {%0, %1}, %2;" : "=f"(x), "=f"(y) : "l"(v));
}
static __device__ __forceinline__ void fma2(ull& d, ull a, ull b) {
    asm("fma.rn.f32x2 %0, %1, %2, %0;" : "+l"(d) : "l"(a), "l"(b));
}
static __device__ __forceinline__ ull mul2(ull a, ull b) {
    ull r;
    asm("mul.rn.f32x2 %0, %1, %2;" : "=l"(r) : "l"(a), "l"(b));
    return r;
}
static __device__ __forceinline__ ull add2(ull a, ull b) {
    ull r;
    asm("add.rn.f32x2 %0, %1, %2;" : "=l"(r) : "l"(a), "l"(b));
    return r;
}

// ---------- Kernel A: k mean over L per (h, d) ----------
__global__ void kmean_kernel(const float* __restrict__ k) {
    __shared__ float red[512];
    const int h = blockIdx.x;
    const int t = threadIdx.x;
    const int d = t & 63;
    const int g = t >> 6;
    const float* src = k + ((size_t)h * LL + (size_t)g * 1024) * DD + d;
    float s = 0.f;
#pragma unroll 8
    for (int r = 0; r < 1024; ++r) s += src[(size_t)r * DD];
    red[t] = s;
    __syncthreads();
    if (t < 64) {
        float tot = 0.f;
#pragma unroll
        for (int gg = 0; gg < 8; ++gg) tot += red[t + 64 * gg];
        g_kmean[h * DD + t] = tot * (1.f / 8192.f);
    }
}

// ---------- Kernel B: block pools ----------
__global__ void pool_kernel(const float* __restrict__ q, const float* __restrict__ k) {
    const int m = blockIdx.x;
    const int h = blockIdx.y;
    const int d = threadIdx.x;
    const float* base = (blockIdx.z == 0 ? q : k);
    const float* src = base + ((size_t)h * LL + (size_t)m * 64) * DD + d;
    float s = 0.f;
#pragma unroll 8
    for (int r = 0; r < 64; ++r) s += src[r * DD];
    s *= (1.f / 64.f);
    if (blockIdx.z == 0)
        g_qpool[(h * MB + m) * DD + d] = s;
    else
        g_kpool[(h * NBLK + m) * DD + d] = s - g_kmean[h * DD + d];
}

// ---------- Kernel C: block scores + top-16 LUT ----------
__global__ void lut_kernel() {
    __shared__ float qrow[64];
    __shared__ float kp[128 * 65];
    __shared__ float sc[128];
    const int m = blockIdx.x;
    const int h = blockIdx.y;
    const int t = threadIdx.x;

    if (t < 64) qrow[t] = g_qpool[(h * MB + m) * DD + t];
    for (int i = t; i < 128 * 64; i += 128) {
        int n = i >> 6, d = i & 63;
        kp[n * 65 + d] = g_kpool[(h * NBLK + n) * DD + d];
    }
    __syncthreads();

    float acc = 0.f;
#pragma unroll 8
    for (int d = 0; d < 64; ++d) acc += qrow[d] * kp[t * 65 + d];
    sc[t] = acc;
    __syncthreads();

    if (t < 32) {
        for (int r = 0; r < TSEL; ++r) {
            float bv = -CUDART_INF_F;
            int bi = 0;
#pragma unroll
            for (int kk = 0; kk < 4; ++kk) {
                int n = t + 32 * kk;
                float v = sc[n];
                if (v > bv || (v == bv && n < bi)) { bv = v; bi = n; }
            }
#pragma unroll
            for (int s = 16; s > 0; s >>= 1) {
                float ov = __shfl_xor_sync(0xffffffffu, bv, s);
                int   oi = __shfl_xor_sync(0xffffffffu, bi, s);
                if (ov > bv || (ov == bv && oi < bi)) { bv = ov; bi = oi; }
            }
            if (t == 0) {
                g_lut[(h * MB + m) * TSEL + r] = bi;
                sc[bi] = -CUDART_INF_F;
            }
            __syncwarp();
        }
    }
}

// ---------- Kernel D: sparse attention (v3: 8x8 register tiles, swizzled smem) ----------
// smem floats: Qt[64][64] | KT[64][128] chunk-sw | Vs[128][64] chunk-sw | Pm[64][132] xor16 | lut
#define SM_QT 0
#define SM_KT 4096
#define SM_V  12288
#define SM_P  20480
#define SM_LUT 28928
#define SMEM_BYTES ((SM_LUT + 16) * 4)

__global__ void __launch_bounds__(128, 2)
attn_kernel(const float* __restrict__ q, const float* __restrict__ k,
            const float* __restrict__ v, float* __restrict__ out) {
    extern __shared__ float sm[];
    float* Qt = sm + SM_QT;
    float* KT = sm + SM_KT;
    float* Vs = sm + SM_V;
    float* Pm = sm + SM_P;
    int* lut = (int*)(sm + SM_LUT);

    const int m = blockIdx.x;
    const int h = blockIdx.y;
    const int t = threadIdx.x;
    const int lane = t & 31;
    const int w = t >> 5;
    const int rg = (lane & 1) + 2 * w;   // 0..7 : thread rows = rg + 8u
    const int cg = lane >> 1;            // 0..15 : S cols = 8cg + j
    const int cgo = cg & 7;              // O dims = 8cgo + j
    const int chf = cg >> 3;             // kv half for O-GEMM

    // K phys offsets (chunk ^ (chunk>>3) swizzle), chunks 2cg, 2cg+1 of [0,32)
    const int kc0 = (((2 * cg)     ^ ((2 * cg)     >> 3)) << 2);
    const int kc1 = (((2 * cg + 1) ^ ((2 * cg + 1) >> 3)) << 2);
    // V phys offsets, chunks 2cgo, 2cgo+1 of [0,16)
    const int vo0 = (((2 * cgo)     ^ ((2 * cgo)     >> 3)) << 2);
    const int vo1 = (((2 * cgo + 1) ^ ((2 * cgo + 1) >> 3)) << 2);
    // P store phys col base
    const int pbase = (8 * cg) ^ (16 * chf);

    // ---- build Qt[d][row] = q[row][d] * 0.125 ----
    {
        const float* qg = q + ((size_t)h * LL + (size_t)m * 64) * DD;
        const int c = t & 63, d0 = t >> 6;
#pragma unroll
        for (int i = 0; i < 8; ++i) {
            int dq = d0 + 2 * i;
            float4 qq = *(const float4*)(qg + c * DD + dq * 4);
            Qt[(dq * 4 + 0) * 64 + c] = qq.x * 0.125f;
            Qt[(dq * 4 + 1) * 64 + c] = qq.y * 0.125f;
            Qt[(dq * 4 + 2) * 64 + c] = qq.z * 0.125f;
            Qt[(dq * 4 + 3) * 64 + c] = qq.w * 0.125f;
        }
    }
    if (t < TSEL) lut[t] = g_lut[(h * MB + m) * TSEL + t];

    ull o2[8][4];
    float mrow[8], lrow[8];
#pragma unroll
    for (int u = 0; u < 8; ++u) {
        mrow[u] = -CUDART_INF_F;
        lrow[u] = 0.f;
        o2[u][0] = 0ull; o2[u][1] = 0ull; o2[u][2] = 0ull; o2[u][3] = 0ull;
    }

    const float* kg = k + (size_t)h * LL * DD;
    const float* vg = v + (size_t)h * LL * DD;

    for (int bt = 0; bt < 8; ++bt) {
        __syncthreads();
        const int nb0 = lut[2 * bt + 0];
        const int nb1 = lut[2 * bt + 1];
        const float* kb0 = kg + (size_t)nb0 * 64 * DD;
        const float* kb1 = kg + (size_t)nb1 * 64 * DD;
        const float* vb0 = vg + (size_t)nb0 * 64 * DD;
        const float* vb1 = vg + (size_t)nb1 * 64 * DD;

        // ---- KT[d][col] = K[col%64][d], cols chunk-swizzled ----
        {
            const int c = t & 63, d0 = t >> 6;
#pragma unroll
            for (int b = 0; b < 2; ++b) {
                const float* kb = b ? kb1 : kb0;
                const int col = b * 64 + c;
                const int pc = (((col >> 2) ^ ((col >> 2) >> 3)) << 2) + (col & 3);
#pragma unroll
                for (int i = 0; i < 8; ++i) {
                    int dq = d0 + 2 * i;
                    float4 kk = *(const float4*)(kb + c * DD + dq * 4);
                    KT[(dq * 4 + 0) * 128 + pc] = kk.x;
                    KT[(dq * 4 + 1) * 128 + pc] = kk.y;
                    KT[(dq * 4 + 2) * 128 + pc] = kk.z;
                    KT[(dq * 4 + 3) * 128 + pc] = kk.w;
                }
            }
        }
        // ---- Vs[c][d] chunk-swizzled ----
#pragma unroll
        for (int r = 0; r < 16; ++r) {
            int i4 = t + 128 * r;
            int c = i4 >> 4, dq = i4 & 15;
            const float* vb = (c < 64) ? (vb0 + c * DD) : (vb1 + (c - 64) * DD);
            float4 vv = *(const float4*)(vb + dq * 4);
            int pd = ((dq ^ (dq >> 3)) << 2);
            *(float4*)(Vs + c * 64 + pd) = vv;
        }
        __syncthreads();

        // ---- S = (Q*scale) @ K^T : per-thread 8 rows x 8 cols ----
        ull s2[8][4];
#pragma unroll
        for (int u = 0; u < 8; ++u) {
            s2[u][0] = 0ull; s2[u][1] = 0ull; s2[u][2] = 0ull; s2[u][3] = 0ull;
        }
#pragma unroll 2
        for (int d = 0; d < 64; ++d) {
            const float* KTd = KT + d * 128;
            const ulonglong2 k0 = *(const ulonglong2*)(KTd + kc0);
            const ulonglong2 k1 = *(const ulonglong2*)(KTd + kc1);
            const float* Qd = Qt + d * 64 + rg;
#pragma unroll
            for (int u = 0; u < 8; ++u) {
                float qv = Qd[8 * u];
                ull q2 = pk2(qv, qv);
                fma2(s2[u][0], q2, k0.x);
                fma2(s2[u][1], q2, k0.y);
                fma2(s2[u][2], q2, k1.x);
                fma2(s2[u][3], q2, k1.y);
            }
        }

        // ---- online softmax; stats reduced over the 16 cg lanes (masks 2,4,8,16) ----
#pragma unroll
        for (int u = 0; u < 8; ++u) {
            float vals[8];
            upk2(s2[u][0], vals[0], vals[1]);
            upk2(s2[u][1], vals[2], vals[3]);
            upk2(s2[u][2], vals[4], vals[5]);
            upk2(s2[u][3], vals[6], vals[7]);
            float mx = vals[0];
#pragma unroll
            for (int j = 1; j < 8; ++j) mx = fmaxf(mx, vals[j]);
#pragma unroll
            for (int s = 2; s <= 16; s <<= 1)
                mx = fmaxf(mx, __shfl_xor_sync(0xffffffffu, mx, s));
            float mnew = fmaxf(mrow[u], mx);
            float alpha = __expf(mrow[u] - mnew);
            mrow[u] = mnew;
            float rs = 0.f;
#pragma unroll
            for (int j = 0; j < 8; ++j) {
                vals[j] = __expf(vals[j] - mnew);
                rs += vals[j];
            }
#pragma unroll
            for (int s = 2; s <= 16; s <<= 1)
                rs += __shfl_xor_sync(0xffffffffu, rs, s);
            lrow[u] = lrow[u] * alpha + rs;
            ull a2 = pk2(alpha, alpha);
            o2[u][0] = mul2(o2[u][0], a2);
            o2[u][1] = mul2(o2[u][1], a2);
            o2[u][2] = mul2(o2[u][2], a2);
            o2[u][3] = mul2(o2[u][3], a2);
            float* pr = Pm + (rg + 8 * u) * 132 + pbase;
            *(float4*)(pr + 0) = make_float4(vals[0], vals[1], vals[2], vals[3]);
            *(float4*)(pr + 4) = make_float4(vals[4], vals[5], vals[6], vals[7]);
        }
        __syncthreads();

        // ---- O += P @ V : each lane-half handles 64 kv of its half ----
        const int cbase = chf * 64;
#pragma unroll 2
        for (int cc = 0; cc < 64; ++cc) {
            const int pc = chf ? (64 + (cc ^ 16)) : cc;
            const float* Vc = Vs + (cbase + cc) * 64;
            const ulonglong2 v0 = *(const ulonglong2*)(Vc + vo0);
            const ulonglong2 v1 = *(const ulonglong2*)(Vc + vo1);
            const float* Pc = Pm + rg * 132 + pc;
#pragma unroll
            for (int u = 0; u < 8; ++u) {
                float pv = Pc[1056 * u];  // (rg+8u)*132 + pc
                ull p2 = pk2(pv, pv);
                fma2(o2[u][0], p2, v0.x);
                fma2(o2[u][1], p2, v0.y);
                fma2(o2[u][2], p2, v1.x);
                fma2(o2[u][3], p2, v1.y);
            }
        }
    }

    // ---- merge kv halves (lanes cg and cg^8 == lane^16), normalize, write ----
#pragma unroll
    for (int u = 0; u < 8; ++u) {
#pragma unroll
        for (int jj = 0; jj < 4; ++jj) {
            ull o = __shfl_xor_sync(0xffffffffu, o2[u][jj], 16);
            o2[u][jj] = add2(o2[u][jj], o);
        }
    }
    if (chf == 0) {
        float* og = out + ((size_t)h * LL + (size_t)m * 64) * DD;
#pragma unroll
        for (int u = 0; u < 8; ++u) {
            const float inv = 1.0f / lrow[u];
            float a, b, c2, d2;
            upk2(o2[u][0], a, b);
            upk2(o2[u][1], c2, d2);
            *(float4*)(og + (rg + 8 * u) * DD + 8 * cgo) =
                make_float4(a * inv, b * inv, c2 * inv, d2 * inv);
            upk2(o2[u][2], a, b);
            upk2(o2[u][3], c2, d2);
            *(float4*)(og + (rg + 8 * u) * DD + 8 * cgo + 4) =
                make_float4(a * inv, b * inv, c2 * inv, d2 * inv);
        }
    }
}

extern "C" void kernel_launch(void* const* d_in, const int* in_sizes, int n_in,
                              void* d_out, int out_size) {
    const float* q = (const float*)d_in[0];
    const float* k = (const float*)d_in[1];
    const float* v = (const float*)d_in[2];
    float* out = (float*)d_out;

    cudaFuncSetAttribute(attn_kernel, cudaFuncAttributeMaxDynamicSharedMemorySize, SMEM_BYTES);

    kmean_kernel<<<HH, 512>>>(k);
    pool_kernel<<<dim3(MB, HH, 2), 64>>>(q, k);
    lut_kernel<<<dim3(MB, HH), 128>>>();
    attn_kernel<<<dim3(MB, HH), 128, SMEM_BYTES>>>(q, k, v, out);
}

// round 7
// speedup vs baseline: 1.4210x; 1.2912x over previous
#include <cuda_runtime.h>
#include <math_constants.h>

#define HH   16
#define LL   8192
#define DD   64
#define MB   128
#define NBLK 128
#define TSEL 16

typedef unsigned long long ull;

// scratch (no allocation allowed -> device globals)
__device__ float g_kpart[HH * 32 * DD];
__device__ float g_kmean[HH * DD];
__device__ float g_qpool[HH * MB * DD];
__device__ float g_kpool[HH * NBLK * DD];
__device__ int   g_lut[HH * MB * TSEL];

// ---------- f32x2 helpers (Blackwell packed fp32) ----------
static __device__ __forceinline__ ull pk2(float x, float y) {
    ull r;
    asm("mov.b64 %0, {%1, %2};" : "=l"(r) : "f"(x), "f"(y));
    return r;
}
static __device__ __forceinline__ void upk2(ull v, float& x, float& y) {
    asm("mov.b64 {%0, %1}, %2;" : "=f"(x), "=f"(y) : "l"(v));
}
static __device__ __forceinline__ void fma2(ull& d, ull a, ull b) {
    asm("fma.rn.f32x2 %0, %1, %2, %0;" : "+l"(d) : "l"(a), "l"(b));
}
static __device__ __forceinline__ ull mul2(ull a, ull b) {
    ull r;
    asm("mul.rn.f32x2 %0, %1, %2;" : "=l"(r) : "l"(a), "l"(b));
    return r;
}
static __device__ __forceinline__ ull add2(ull a, ull b) {
    ull r;
    asm("add.rn.f32x2 %0, %1, %2;" : "=l"(r) : "l"(a), "l"(b));
    return r;
}

// ---------- Kernel A1: partial k sums. grid (HH, 32), 256 thr ----------
__global__ void kmean1_kernel(const float* __restrict__ k) {
    __shared__ float red[256];
    const int h = blockIdx.x;
    const int seg = blockIdx.y;
    const int t = threadIdx.x;
    const int d = t & 63;
    const int g = t >> 6;  // 0..3, 64 rows each
    const float* src = k + ((size_t)h * LL + (size_t)seg * 256 + (size_t)g * 64) * DD + d;
    float s = 0.f;
#pragma unroll 8
    for (int r = 0; r < 64; ++r) s += src[(size_t)r * DD];
    red[t] = s;
    __syncthreads();
    if (t < 64) {
        float tot = red[t] + red[t + 64] + red[t + 128] + red[t + 192];
        g_kpart[(h * 32 + seg) * DD + t] = tot;
    }
}

// ---------- Kernel A2: combine partials. grid HH, 64 thr ----------
__global__ void kmean2_kernel() {
    const int h = blockIdx.x;
    const int d = threadIdx.x;
    float tot = 0.f;
#pragma unroll
    for (int s = 0; s < 32; ++s) tot += g_kpart[(h * 32 + s) * DD + d];
    g_kmean[h * DD + d] = tot * (1.f / 8192.f);
}

// ---------- Kernel B: block pools ----------
__global__ void pool_kernel(const float* __restrict__ q, const float* __restrict__ k) {
    const int m = blockIdx.x;
    const int h = blockIdx.y;
    const int d = threadIdx.x;
    const float* base = (blockIdx.z == 0 ? q : k);
    const float* src = base + ((size_t)h * LL + (size_t)m * 64) * DD + d;
    float s = 0.f;
#pragma unroll 8
    for (int r = 0; r < 64; ++r) s += src[r * DD];
    s *= (1.f / 64.f);
    if (blockIdx.z == 0)
        g_qpool[(h * MB + m) * DD + d] = s;
    else
        g_kpool[(h * NBLK + m) * DD + d] = s - g_kmean[h * DD + d];
}

// ---------- Kernel C: block scores + top-16 LUT ----------
__global__ void lut_kernel() {
    __shared__ float qrow[64];
    __shared__ float kp[128 * 65];
    __shared__ float sc[128];
    const int m = blockIdx.x;
    const int h = blockIdx.y;
    const int t = threadIdx.x;

    if (t < 64) qrow[t] = g_qpool[(h * MB + m) * DD + t];
    for (int i = t; i < 128 * 64; i += 128) {
        int n = i >> 6, d = i & 63;
        kp[n * 65 + d] = g_kpool[(h * NBLK + n) * DD + d];
    }
    __syncthreads();

    float acc = 0.f;
#pragma unroll 8
    for (int d = 0; d < 64; ++d) acc += qrow[d] * kp[t * 65 + d];
    sc[t] = acc;
    __syncthreads();

    if (t < 32) {
        for (int r = 0; r < TSEL; ++r) {
            float bv = -CUDART_INF_F;
            int bi = 0;
#pragma unroll
            for (int kk = 0; kk < 4; ++kk) {
                int n = t + 32 * kk;
                float v = sc[n];
                if (v > bv || (v == bv && n < bi)) { bv = v; bi = n; }
            }
#pragma unroll
            for (int s = 16; s > 0; s >>= 1) {
                float ov = __shfl_xor_sync(0xffffffffu, bv, s);
                int   oi = __shfl_xor_sync(0xffffffffu, bi, s);
                if (ov > bv || (ov == bv && oi < bi)) { bv = ov; bi = oi; }
            }
            if (t == 0) {
                g_lut[(h * MB + m) * TSEL + r] = bi;
                sc[bi] = -CUDART_INF_F;
            }
            __syncwarp();
        }
    }
}

// ---------- Kernel D: sparse attention (v4: 8x8 reg tiles, 2 CTAs/SM) ----------
// smem floats: Qt[64][64] | KT[64][128] chunk-sw | Vs[128][64] chunk-sw | Pm[64][132]
// LUT lives in Pm's padding column 128 (rows 0..15) - never touched by P traffic.
#define SM_QT 0
#define SM_KT 4096
#define SM_V  12288
#define SM_P  20480
#define SMEM_FLOATS (SM_P + 64 * 132)      /* 28928 */
#define SMEM_BYTES  (SMEM_FLOATS * 4)      /* 115712 = exactly 113 KB */
#define LUT_AT(i) (*(int*)(Pm + (i) * 132 + 128))

__global__ void __launch_bounds__(128, 2)
attn_kernel(const float* __restrict__ q, const float* __restrict__ k,
            const float* __restrict__ v, float* __restrict__ out) {
    extern __shared__ float sm[];
    float* Qt = sm + SM_QT;
    float* KT = sm + SM_KT;
    float* Vs = sm + SM_V;
    float* Pm = sm + SM_P;

    const int m = blockIdx.x;
    const int h = blockIdx.y;
    const int t = threadIdx.x;
    const int lane = t & 31;
    const int w = t >> 5;
    const int rg = (lane & 1) + 2 * w;   // 0..7 : thread rows = rg + 8u
    const int cg = lane >> 1;            // 0..15 : S cols = 8cg + j
    const int cgo = cg & 7;              // O dims = 8cgo + j
    const int chf = cg >> 3;             // kv half for O-GEMM

    // K phys offsets (chunk ^ (chunk>>3) swizzle), chunks 2cg, 2cg+1 of [0,32)
    const int kc0 = (((2 * cg)     ^ ((2 * cg)     >> 3)) << 2);
    const int kc1 = (((2 * cg + 1) ^ ((2 * cg + 1) >> 3)) << 2);
    // V phys offsets, chunks 2cgo, 2cgo+1 of [0,16)
    const int vo0 = (((2 * cgo)     ^ ((2 * cgo)     >> 3)) << 2);
    const int vo1 = (((2 * cgo + 1) ^ ((2 * cgo + 1) >> 3)) << 2);
    // P store phys col base
    const int pbase = (8 * cg) ^ (16 * chf);

    // ---- build Qt[d][row] = q[row][d] * 0.125 ----
    {
        const float* qg = q + ((size_t)h * LL + (size_t)m * 64) * DD;
        const int c = t & 63, d0 = t >> 6;
#pragma unroll
        for (int i = 0; i < 8; ++i) {
            int dq = d0 + 2 * i;
            float4 qq = *(const float4*)(qg + c * DD + dq * 4);
            Qt[(dq * 4 + 0) * 64 + c] = qq.x * 0.125f;
            Qt[(dq * 4 + 1) * 64 + c] = qq.y * 0.125f;
            Qt[(dq * 4 + 2) * 64 + c] = qq.z * 0.125f;
            Qt[(dq * 4 + 3) * 64 + c] = qq.w * 0.125f;
        }
    }
    if (t < TSEL) LUT_AT(t) = g_lut[(h * MB + m) * TSEL + t];

    ull o2[8][4];
    float mrow[8], lrow[8];
#pragma unroll
    for (int u = 0; u < 8; ++u) {
        mrow[u] = -CUDART_INF_F;
        lrow[u] = 0.f;
        o2[u][0] = 0ull; o2[u][1] = 0ull; o2[u][2] = 0ull; o2[u][3] = 0ull;
    }

    const float* kg = k + (size_t)h * LL * DD;
    const float* vg = v + (size_t)h * LL * DD;

    for (int bt = 0; bt < 8; ++bt) {
        __syncthreads();
        const int nb0 = LUT_AT(2 * bt + 0);
        const int nb1 = LUT_AT(2 * bt + 1);
        const float* kb0 = kg + (size_t)nb0 * 64 * DD;
        const float* kb1 = kg + (size_t)nb1 * 64 * DD;
        const float* vb0 = vg + (size_t)nb0 * 64 * DD;
        const float* vb1 = vg + (size_t)nb1 * 64 * DD;

        // ---- KT[d][col] = K[col%64][d], cols chunk-swizzled ----
        {
            const int c = t & 63, d0 = t >> 6;
#pragma unroll
            for (int b = 0; b < 2; ++b) {
                const float* kb = b ? kb1 : kb0;
                const int col = b * 64 + c;
                const int pc = (((col >> 2) ^ ((col >> 2) >> 3)) << 2) + (col & 3);
#pragma unroll
                for (int i = 0; i < 8; ++i) {
                    int dq = d0 + 2 * i;
                    float4 kk = *(const float4*)(kb + c * DD + dq * 4);
                    KT[(dq * 4 + 0) * 128 + pc] = kk.x;
                    KT[(dq * 4 + 1) * 128 + pc] = kk.y;
                    KT[(dq * 4 + 2) * 128 + pc] = kk.z;
                    KT[(dq * 4 + 3) * 128 + pc] = kk.w;
                }
            }
        }
        // ---- Vs[c][d] chunk-swizzled ----
#pragma unroll
        for (int r = 0; r < 16; ++r) {
            int i4 = t + 128 * r;
            int c = i4 >> 4, dq = i4 & 15;
            const float* vb = (c < 64) ? (vb0 + c * DD) : (vb1 + (c - 64) * DD);
            float4 vv = *(const float4*)(vb + dq * 4);
            int pd = ((dq ^ (dq >> 3)) << 2);
            *(float4*)(Vs + c * 64 + pd) = vv;
        }
        __syncthreads();

        // ---- S = (Q*scale) @ K^T : per-thread 8 rows x 8 cols ----
        ull s2[8][4];
#pragma unroll
        for (int u = 0; u < 8; ++u) {
            s2[u][0] = 0ull; s2[u][1] = 0ull; s2[u][2] = 0ull; s2[u][3] = 0ull;
        }
#pragma unroll 2
        for (int d = 0; d < 64; ++d) {
            const float* KTd = KT + d * 128;
            const ulonglong2 k0 = *(const ulonglong2*)(KTd + kc0);
            const ulonglong2 k1 = *(const ulonglong2*)(KTd + kc1);
            const float* Qd = Qt + d * 64 + rg;
#pragma unroll
            for (int u = 0; u < 8; ++u) {
                float qv = Qd[8 * u];
                ull q2 = pk2(qv, qv);
                fma2(s2[u][0], q2, k0.x);
                fma2(s2[u][1], q2, k0.y);
                fma2(s2[u][2], q2, k1.x);
                fma2(s2[u][3], q2, k1.y);
            }
        }

        // ---- online softmax; stats reduced over the 16 cg lanes (masks 2..16) ----
#pragma unroll
        for (int u = 0; u < 8; ++u) {
            float vals[8];
            upk2(s2[u][0], vals[0], vals[1]);
            upk2(s2[u][1], vals[2], vals[3]);
            upk2(s2[u][2], vals[4], vals[5]);
            upk2(s2[u][3], vals[6], vals[7]);
            float mx = vals[0];
#pragma unroll
            for (int j = 1; j < 8; ++j) mx = fmaxf(mx, vals[j]);
#pragma unroll
            for (int s = 2; s <= 16; s <<= 1)
                mx = fmaxf(mx, __shfl_xor_sync(0xffffffffu, mx, s));
            float mnew = fmaxf(mrow[u], mx);
            float alpha = __expf(mrow[u] - mnew);
            mrow[u] = mnew;
            float rs = 0.f;
#pragma unroll
            for (int j = 0; j < 8; ++j) {
                vals[j] = __expf(vals[j] - mnew);
                rs += vals[j];
            }
#pragma unroll
            for (int s = 2; s <= 16; s <<= 1)
                rs += __shfl_xor_sync(0xffffffffu, rs, s);
            lrow[u] = lrow[u] * alpha + rs;
            ull a2 = pk2(alpha, alpha);
            o2[u][0] = mul2(o2[u][0], a2);
            o2[u][1] = mul2(o2[u][1], a2);
            o2[u][2] = mul2(o2[u][2], a2);
            o2[u][3] = mul2(o2[u][3], a2);
            float* pr = Pm + (rg + 8 * u) * 132 + pbase;
            *(float4*)(pr + 0) = make_float4(vals[0], vals[1], vals[2], vals[3]);
            *(float4*)(pr + 4) = make_float4(vals[4], vals[5], vals[6], vals[7]);
        }
        __syncthreads();

        // ---- O += P @ V : each lane-half handles 64 kv of its half ----
        const int cbase = chf * 64;
#pragma unroll 2
        for (int cc = 0; cc < 64; ++cc) {
            const int pc = chf ? (64 + (cc ^ 16)) : cc;
            const float* Vc = Vs + (cbase + cc) * 64;
            const ulonglong2 v0 = *(const ulonglong2*)(Vc + vo0);
            const ulonglong2 v1 = *(const ulonglong2*)(Vc + vo1);
            const float* Pc = Pm + rg * 132 + pc;
#pragma unroll
            for (int u = 0; u < 8; ++u) {
                float pv = Pc[1056 * u];  // (rg+8u)*132 + pc
                ull p2 = pk2(pv, pv);
                fma2(o2[u][0], p2, v0.x);
                fma2(o2[u][1], p2, v0.y);
                fma2(o2[u][2], p2, v1.x);
                fma2(o2[u][3], p2, v1.y);
            }
        }
    }

    // ---- merge kv halves (lane ^ 16), normalize, write ----
#pragma unroll
    for (int u = 0; u < 8; ++u) {
#pragma unroll
        for (int jj = 0; jj < 4; ++jj) {
            ull o = __shfl_xor_sync(0xffffffffu, o2[u][jj], 16);
            o2[u][jj] = add2(o2[u][jj], o);
        }
    }
    if (chf == 0) {
        float* og = out + ((size_t)h * LL + (size_t)m * 64) * DD;
#pragma unroll
        for (int u = 0; u < 8; ++u) {
            const float inv = 1.0f / lrow[u];
            float a, b, c2, d2;
            upk2(o2[u][0], a, b);
            upk2(o2[u][1], c2, d2);
            *(float4*)(og + (rg + 8 * u) * DD + 8 * cgo) =
                make_float4(a * inv, b * inv, c2 * inv, d2 * inv);
            upk2(o2[u][2], a, b);
            upk2(o2[u][3], c2, d2);
            *(float4*)(og + (rg + 8 * u) * DD + 8 * cgo + 4) =
                make_float4(a * inv, b * inv, c2 * inv, d2 * inv);
        }
    }
}

extern "C" void kernel_launch(void* const* d_in, const int* in_sizes, int n_in,
                              void* d_out, int out_size) {
    const float* q = (const float*)d_in[0];
    const float* k = (const float*)d_in[1];
    const float* v = (const float*)d_in[2];
    float* out = (float*)d_out;

    cudaFuncSetAttribute(attn_kernel, cudaFuncAttributeMaxDynamicSharedMemorySize, SMEM_BYTES);

    kmean1_kernel<<<dim3(HH, 32), 256>>>(k);
    kmean2_kernel<<<HH, 64>>>();
    pool_kernel<<<dim3(MB, HH, 2), 64>>>(q, k);
    lut_kernel<<<dim3(MB, HH), 128>>>();
    attn_kernel<<<dim3(MB, HH), 128, SMEM_BYTES>>>(q, k, v, out);
}

// round 8
// speedup vs baseline: 1.4217x; 1.0005x over previous
#include <cuda_runtime.h>
#include <math_constants.h>

#define HH   16
#define LL   8192
#define DD   64
#define MB   128
#define NBLK 128
#define TSEL 16

typedef unsigned long long ull;

// scratch (no allocation allowed -> device globals)
__device__ float g_kpart[HH * 32 * DD];
__device__ float g_kmean[HH * DD];
__device__ float g_qpool[HH * MB * DD];
__device__ float g_kpool[HH * NBLK * DD];
__device__ int   g_lut[HH * MB * TSEL];

// ---------- f32x2 helpers (Blackwell packed fp32) ----------
static __device__ __forceinline__ ull pk2(float x, float y) {
    ull r;
    asm("mov.b64 %0, {%1, %2};" : "=l"(r) : "f"(x), "f"(y));
    return r;
}
static __device__ __forceinline__ void upk2(ull v, float& x, float& y) {
    asm("mov.b64 {%0, %1}, %2;" : "=f"(x), "=f"(y) : "l"(v));
}
static __device__ __forceinline__ void fma2(ull& d, ull a, ull b) {
    asm("fma.rn.f32x2 %0, %1, %2, %0;" : "+l"(d) : "l"(a), "l"(b));
}
static __device__ __forceinline__ ull mul2(ull a, ull b) {
    ull r;
    asm("mul.rn.f32x2 %0, %1, %2;" : "=l"(r) : "l"(a), "l"(b));
    return r;
}
static __device__ __forceinline__ ull add2(ull a, ull b) {
    ull r;
    asm("add.rn.f32x2 %0, %1, %2;" : "=l"(r) : "l"(a), "l"(b));
    return r;
}

// ---------- Kernel A1: partial k sums. grid (HH, 32), 256 thr ----------
__global__ void kmean1_kernel(const float* __restrict__ k) {
    __shared__ float red[256];
    const int h = blockIdx.x;
    const int seg = blockIdx.y;
    const int t = threadIdx.x;
    const int d = t & 63;
    const int g = t >> 6;  // 0..3, 64 rows each
    const float* src = k + ((size_t)h * LL + (size_t)seg * 256 + (size_t)g * 64) * DD + d;
    float s = 0.f;
#pragma unroll 8
    for (int r = 0; r < 64; ++r) s += src[(size_t)r * DD];
    red[t] = s;
    __syncthreads();
    if (t < 64) {
        float tot = red[t] + red[t + 64] + red[t + 128] + red[t + 192];
        g_kpart[(h * 32 + seg) * DD + t] = tot;
    }
}

// ---------- Kernel A2: combine partials. grid HH, 64 thr ----------
__global__ void kmean2_kernel() {
    const int h = blockIdx.x;
    const int d = threadIdx.x;
    float tot = 0.f;
#pragma unroll
    for (int s = 0; s < 32; ++s) tot += g_kpart[(h * 32 + s) * DD + d];
    g_kmean[h * DD + d] = tot * (1.f / 8192.f);
}

// ---------- Kernel B: block pools ----------
__global__ void pool_kernel(const float* __restrict__ q, const float* __restrict__ k) {
    const int m = blockIdx.x;
    const int h = blockIdx.y;
    const int d = threadIdx.x;
    const float* base = (blockIdx.z == 0 ? q : k);
    const float* src = base + ((size_t)h * LL + (size_t)m * 64) * DD + d;
    float s = 0.f;
#pragma unroll 8
    for (int r = 0; r < 64; ++r) s += src[r * DD];
    s *= (1.f / 64.f);
    if (blockIdx.z == 0)
        g_qpool[(h * MB + m) * DD + d] = s;
    else
        g_kpool[(h * NBLK + m) * DD + d] = s - g_kmean[h * DD + d];
}

// ---------- Kernel C: block scores + top-16 LUT ----------
__global__ void lut_kernel() {
    __shared__ float qrow[64];
    __shared__ float kp[128 * 65];
    __shared__ float sc[128];
    const int m = blockIdx.x;
    const int h = blockIdx.y;
    const int t = threadIdx.x;

    if (t < 64) qrow[t] = g_qpool[(h * MB + m) * DD + t];
    for (int i = t; i < 128 * 64; i += 128) {
        int n = i >> 6, d = i & 63;
        kp[n * 65 + d] = g_kpool[(h * NBLK + n) * DD + d];
    }
    __syncthreads();

    float acc = 0.f;
#pragma unroll 8
    for (int d = 0; d < 64; ++d) acc += qrow[d] * kp[t * 65 + d];
    sc[t] = acc;
    __syncthreads();

    if (t < 32) {
        for (int r = 0; r < TSEL; ++r) {
            float bv = -CUDART_INF_F;
            int bi = 0;
#pragma unroll
            for (int kk = 0; kk < 4; ++kk) {
                int n = t + 32 * kk;
                float v = sc[n];
                if (v > bv || (v == bv && n < bi)) { bv = v; bi = n; }
            }
#pragma unroll
            for (int s = 16; s > 0; s >>= 1) {
                float ov = __shfl_xor_sync(0xffffffffu, bv, s);
                int   oi = __shfl_xor_sync(0xffffffffu, bi, s);
                if (ov > bv || (ov == bv && oi < bi)) { bv = ov; bi = oi; }
            }
            if (t == 0) {
                g_lut[(h * MB + m) * TSEL + r] = bi;
                sc[bi] = -CUDART_INF_F;
            }
            __syncwarp();
        }
    }
}

// ---------- Kernel D: sparse attention (v4: 8x8 reg tiles, 2 CTAs/SM) ----------
// smem floats: Qt[64][64] | KT[64][128] chunk-sw | Vs[128][64] chunk-sw | Pm[64][132]
// LUT lives in Pm's padding column 128 (rows 0..15) - never touched by P traffic.
#define SM_QT 0
#define SM_KT 4096
#define SM_V  12288
#define SM_P  20480
#define SMEM_FLOATS (SM_P + 64 * 132)      /* 28928 */
#define SMEM_BYTES  (SMEM_FLOATS * 4)      /* 115712 = exactly 113 KB */
#define LUT_AT(i) (*(int*)(Pm + (i) * 132 + 128))

__global__ void __launch_bounds__(128, 2)
attn_kernel(const float* __restrict__ q, const float* __restrict__ k,
            const float* __restrict__ v, float* __restrict__ out) {
    extern __shared__ float sm[];
    float* Qt = sm + SM_QT;
    float* KT = sm + SM_KT;
    float* Vs = sm + SM_V;
    float* Pm = sm + SM_P;

    const int m = blockIdx.x;
    const int h = blockIdx.y;
    const int t = threadIdx.x;
    const int lane = t & 31;
    const int w = t >> 5;
    const int rg = (lane & 1) + 2 * w;   // 0..7 : thread rows = rg + 8u
    const int cg = lane >> 1;            // 0..15 : S cols = 8cg + j
    const int cgo = cg & 7;              // O dims = 8cgo + j
    const int chf = cg >> 3;             // kv half for O-GEMM

    // K phys offsets (chunk ^ (chunk>>3) swizzle), chunks 2cg, 2cg+1 of [0,32)
    const int kc0 = (((2 * cg)     ^ ((2 * cg)     >> 3)) << 2);
    const int kc1 = (((2 * cg + 1) ^ ((2 * cg + 1) >> 3)) << 2);
    // V phys offsets, chunks 2cgo, 2cgo+1 of [0,16)
    const int vo0 = (((2 * cgo)     ^ ((2 * cgo)     >> 3)) << 2);
    const int vo1 = (((2 * cgo + 1) ^ ((2 * cgo + 1) >> 3)) << 2);
    // P store phys col base
    const int pbase = (8 * cg) ^ (16 * chf);

    // ---- build Qt[d][row] = q[row][d] * 0.125 ----
    {
        const float* qg = q + ((size_t)h * LL + (size_t)m * 64) * DD;
        const int c = t & 63, d0 = t >> 6;
#pragma unroll
        for (int i = 0; i < 8; ++i) {
            int dq = d0 + 2 * i;
            float4 qq = *(const float4*)(qg + c * DD + dq * 4);
            Qt[(dq * 4 + 0) * 64 + c] = qq.x * 0.125f;
            Qt[(dq * 4 + 1) * 64 + c] = qq.y * 0.125f;
            Qt[(dq * 4 + 2) * 64 + c] = qq.z * 0.125f;
            Qt[(dq * 4 + 3) * 64 + c] = qq.w * 0.125f;
        }
    }
    if (t < TSEL) LUT_AT(t) = g_lut[(h * MB + m) * TSEL + t];

    ull o2[8][4];
    float mrow[8], lrow[8];
#pragma unroll
    for (int u = 0; u < 8; ++u) {
        mrow[u] = -CUDART_INF_F;
        lrow[u] = 0.f;
        o2[u][0] = 0ull; o2[u][1] = 0ull; o2[u][2] = 0ull; o2[u][3] = 0ull;
    }

    const float* kg = k + (size_t)h * LL * DD;
    const float* vg = v + (size_t)h * LL * DD;

    for (int bt = 0; bt < 8; ++bt) {
        __syncthreads();
        const int nb0 = LUT_AT(2 * bt + 0);
        const int nb1 = LUT_AT(2 * bt + 1);
        const float* kb0 = kg + (size_t)nb0 * 64 * DD;
        const float* kb1 = kg + (size_t)nb1 * 64 * DD;
        const float* vb0 = vg + (size_t)nb0 * 64 * DD;
        const float* vb1 = vg + (size_t)nb1 * 64 * DD;

        // ---- KT[d][col] = K[col%64][d], cols chunk-swizzled ----
        {
            const int c = t & 63, d0 = t >> 6;
#pragma unroll
            for (int b = 0; b < 2; ++b) {
                const float* kb = b ? kb1 : kb0;
                const int col = b * 64 + c;
                const int pc = (((col >> 2) ^ ((col >> 2) >> 3)) << 2) + (col & 3);
#pragma unroll
                for (int i = 0; i < 8; ++i) {
                    int dq = d0 + 2 * i;
                    float4 kk = *(const float4*)(kb + c * DD + dq * 4);
                    KT[(dq * 4 + 0) * 128 + pc] = kk.x;
                    KT[(dq * 4 + 1) * 128 + pc] = kk.y;
                    KT[(dq * 4 + 2) * 128 + pc] = kk.z;
                    KT[(dq * 4 + 3) * 128 + pc] = kk.w;
                }
            }
        }
        // ---- Vs[c][d] chunk-swizzled ----
#pragma unroll
        for (int r = 0; r < 16; ++r) {
            int i4 = t + 128 * r;
            int c = i4 >> 4, dq = i4 & 15;
            const float* vb = (c < 64) ? (vb0 + c * DD) : (vb1 + (c - 64) * DD);
            float4 vv = *(const float4*)(vb + dq * 4);
            int pd = ((dq ^ (dq >> 3)) << 2);
            *(float4*)(Vs + c * 64 + pd) = vv;
        }
        __syncthreads();

        // ---- S = (Q*scale) @ K^T : per-thread 8 rows x 8 cols ----
        ull s2[8][4];
#pragma unroll
        for (int u = 0; u < 8; ++u) {
            s2[u][0] = 0ull; s2[u][1] = 0ull; s2[u][2] = 0ull; s2[u][3] = 0ull;
        }
#pragma unroll 2
        for (int d = 0; d < 64; ++d) {
            const float* KTd = KT + d * 128;
            const ulonglong2 k0 = *(const ulonglong2*)(KTd + kc0);
            const ulonglong2 k1 = *(const ulonglong2*)(KTd + kc1);
            const float* Qd = Qt + d * 64 + rg;
#pragma unroll
            for (int u = 0; u < 8; ++u) {
                float qv = Qd[8 * u];
                ull q2 = pk2(qv, qv);
                fma2(s2[u][0], q2, k0.x);
                fma2(s2[u][1], q2, k0.y);
                fma2(s2[u][2], q2, k1.x);
                fma2(s2[u][3], q2, k1.y);
            }
        }

        // ---- online softmax; stats reduced over the 16 cg lanes (masks 2..16) ----
#pragma unroll
        for (int u = 0; u < 8; ++u) {
            float vals[8];
            upk2(s2[u][0], vals[0], vals[1]);
            upk2(s2[u][1], vals[2], vals[3]);
            upk2(s2[u][2], vals[4], vals[5]);
            upk2(s2[u][3], vals[6], vals[7]);
            float mx = vals[0];
#pragma unroll
            for (int j = 1; j < 8; ++j) mx = fmaxf(mx, vals[j]);
#pragma unroll
            for (int s = 2; s <= 16; s <<= 1)
                mx = fmaxf(mx, __shfl_xor_sync(0xffffffffu, mx, s));
            float mnew = fmaxf(mrow[u], mx);
            float alpha = __expf(mrow[u] - mnew);
            mrow[u] = mnew;
            float rs = 0.f;
#pragma unroll
            for (int j = 0; j < 8; ++j) {
                vals[j] = __expf(vals[j] - mnew);
                rs += vals[j];
            }
#pragma unroll
            for (int s = 2; s <= 16; s <<= 1)
                rs += __shfl_xor_sync(0xffffffffu, rs, s);
            lrow[u] = lrow[u] * alpha + rs;
            ull a2 = pk2(alpha, alpha);
            o2[u][0] = mul2(o2[u][0], a2);
            o2[u][1] = mul2(o2[u][1], a2);
            o2[u][2] = mul2(o2[u][2], a2);
            o2[u][3] = mul2(o2[u][3], a2);
            float* pr = Pm + (rg + 8 * u) * 132 + pbase;
            *(float4*)(pr + 0) = make_float4(vals[0], vals[1], vals[2], vals[3]);
            *(float4*)(pr + 4) = make_float4(vals[4], vals[5], vals[6], vals[7]);
        }
        __syncthreads();

        // ---- O += P @ V : each lane-half handles 64 kv of its half ----
        const int cbase = chf * 64;
#pragma unroll 2
        for (int cc = 0; cc < 64; ++cc) {
            const int pc = chf ? (64 + (cc ^ 16)) : cc;
            const float* Vc = Vs + (cbase + cc) * 64;
            const ulonglong2 v0 = *(const ulonglong2*)(Vc + vo0);
            const ulonglong2 v1 = *(const ulonglong2*)(Vc + vo1);
            const float* Pc = Pm + rg * 132 + pc;
#pragma unroll
            for (int u = 0; u < 8; ++u) {
                float pv = Pc[1056 * u];  // (rg+8u)*132 + pc
                ull p2 = pk2(pv, pv);
                fma2(o2[u][0], p2, v0.x);
                fma2(o2[u][1], p2, v0.y);
                fma2(o2[u][2], p2, v1.x);
                fma2(o2[u][3], p2, v1.y);
            }
        }
    }

    // ---- merge kv halves (lane ^ 16), normalize, write ----
#pragma unroll
    for (int u = 0; u < 8; ++u) {
#pragma unroll
        for (int jj = 0; jj < 4; ++jj) {
            ull o = __shfl_xor_sync(0xffffffffu, o2[u][jj], 16);
            o2[u][jj] = add2(o2[u][jj], o);
        }
    }
    if (chf == 0) {
        float* og = out + ((size_t)h * LL + (size_t)m * 64) * DD;
#pragma unroll
        for (int u = 0; u < 8; ++u) {
            const float inv = 1.0f / lrow[u];
            float a, b, c2, d2;
            upk2(o2[u][0], a, b);
            upk2(o2[u][1], c2, d2);
            *(float4*)(og + (rg + 8 * u) * DD + 8 * cgo) =
                make_float4(a * inv, b * inv, c2 * inv, d2 * inv);
            upk2(o2[u][2], a, b);
            upk2(o2[u][3], c2, d2);
            *(float4*)(og + (rg + 8 * u) * DD + 8 * cgo + 4) =
                make_float4(a * inv, b * inv, c2 * inv, d2 * inv);
        }
    }
}

extern "C" void kernel_launch(void* const* d_in, const int* in_sizes, int n_in,
                              void* d_out, int out_size) {
    const float* q = (const float*)d_in[0];
    const float* k = (const float*)d_in[1];
    const float* v = (const float*)d_in[2];
    float* out = (float*)d_out;

    cudaFuncSetAttribute(attn_kernel, cudaFuncAttributeMaxDynamicSharedMemorySize, SMEM_BYTES);

    kmean1_kernel<<<dim3(HH, 32), 256>>>(k);
    kmean2_kernel<<<HH, 64>>>();
    pool_kernel<<<dim3(MB, HH, 2), 64>>>(q, k);
    lut_kernel<<<dim3(MB, HH), 128>>>();
    attn_kernel<<<dim3(MB, HH), 128, SMEM_BYTES>>>(q, k, v, out);
}

// round 13
// speedup vs baseline: 2.5265x; 1.7771x over previous
#include <cuda_runtime.h>
#include <cuda_bf16.h>
#include <math_constants.h>
#include <cstdint>

#define HH   16
#define LL   8192
#define DD   64
#define MB   128
#define NBLK 128
#define TSEL 16

// scratch (no allocation allowed -> device globals)
__device__ float g_kpart[HH * 32 * DD];
__device__ float g_kmean[HH * DD];
__device__ float g_qpool[HH * MB * DD];
__device__ float g_kpool[HH * NBLK * DD];
__device__ int   g_lut[HH * MB * TSEL];

// ---------- helpers ----------
static __device__ __forceinline__ uint32_t smem_to_u32(const void* p) {
    uint32_t a;
    asm("{ .reg .u64 t; cvta.to.shared.u64 t, %1; cvt.u32.u64 %0, t; }" : "=r"(a) : "l"(p));
    return a;
}
static __device__ __forceinline__ unsigned pkbf2(float a, float b) {
    __nv_bfloat162 t = __floats2bfloat162_rn(a, b);
    return *reinterpret_cast<unsigned*>(&t);
}
static __device__ __forceinline__ void split1(float x, float& hi, float& lo) {
    __nv_bfloat16 hh = __float2bfloat16(x);
    hi = __bfloat162float(hh);
    lo = x - hi;
}
static __device__ __forceinline__ void packsplit(float a, float b, unsigned& hi, unsigned& lo) {
    float ha, la, hb, lb;
    split1(a, ha, la);
    split1(b, hb, lb);
    hi = pkbf2(ha, hb);
    lo = pkbf2(la, lb);
}
// bf16 mma m16n8k16, D = A*B + D (fp32 accum)
static __device__ __forceinline__ void mma_bf16(float* c, const unsigned* a, unsigned b0, unsigned b1) {
    asm volatile(
        "mma.sync.aligned.m16n8k16.row.col.f32.bf16.bf16.f32 "
        "{%0,%1,%2,%3}, {%4,%5,%6,%7}, {%8,%9}, {%0,%1,%2,%3};"
        : "+f"(c[0]), "+f"(c[1]), "+f"(c[2]), "+f"(c[3])
        : "r"(a[0]), "r"(a[1]), "r"(a[2]), "r"(a[3]), "r"(b0), "r"(b1));
}
static __device__ __forceinline__ void ldsm_x4(unsigned& r0, unsigned& r1, unsigned& r2, unsigned& r3,
                                               uint32_t addr) {
    asm volatile("ldmatrix.sync.aligned.m8n8.x4.shared.b16 {%0,%1,%2,%3}, [%4];"
                 : "=r"(r0), "=r"(r1), "=r"(r2), "=r"(r3) : "r"(addr));
}
static __device__ __forceinline__ void ldsm_x4t(unsigned& r0, unsigned& r1, unsigned& r2, unsigned& r3,
                                                uint32_t addr) {
    asm volatile("ldmatrix.sync.aligned.m8n8.x4.trans.shared.b16 {%0,%1,%2,%3}, [%4];"
                 : "=r"(r0), "=r"(r1), "=r"(r2), "=r"(r3) : "r"(addr));
}
// convert 8 floats -> bf16 hi/lo uint4 pair
static __device__ __forceinline__ void cvt8(const float4 f0, const float4 f1, uint4& hi, uint4& lo) {
    float h0, l0, h1, l1, h2, l2, h3, l3, h4, l4, h5, l5, h6, l6, h7, l7;
    split1(f0.x, h0, l0); split1(f0.y, h1, l1); split1(f0.z, h2, l2); split1(f0.w, h3, l3);
    split1(f1.x, h4, l4); split1(f1.y, h5, l5); split1(f1.z, h6, l6); split1(f1.w, h7, l7);
    hi = make_uint4(pkbf2(h0, h1), pkbf2(h2, h3), pkbf2(h4, h5), pkbf2(h6, h7));
    lo = make_uint4(pkbf2(l0, l1), pkbf2(l2, l3), pkbf2(l4, l5), pkbf2(l6, l7));
}

// ---------- Kernel A1: partial k sums ----------
__global__ void kmean1_kernel(const float* __restrict__ k) {
    __shared__ float red[256];
    const int h = blockIdx.x, seg = blockIdx.y, t = threadIdx.x;
    const int d = t & 63, g = t >> 6;
    const float* src = k + ((size_t)h * LL + (size_t)seg * 256 + (size_t)g * 64) * DD + d;
    float s = 0.f;
#pragma unroll 8
    for (int r = 0; r < 64; ++r) s += src[(size_t)r * DD];
    red[t] = s;
    __syncthreads();
    if (t < 64)
        g_kpart[(h * 32 + seg) * DD + t] = red[t] + red[t + 64] + red[t + 128] + red[t + 192];
}

// ---------- Kernel A2: combine partials ----------
__global__ void kmean2_kernel() {
    const int h = blockIdx.x, d = threadIdx.x;
    float tot = 0.f;
#pragma unroll
    for (int s = 0; s < 32; ++s) tot += g_kpart[(h * 32 + s) * DD + d];
    g_kmean[h * DD + d] = tot * (1.f / 8192.f);
}

// ---------- Kernel B: block pools ----------
__global__ void pool_kernel(const float* __restrict__ q, const float* __restrict__ k) {
    const int m = blockIdx.x, h = blockIdx.y, d = threadIdx.x;
    const float* base = (blockIdx.z == 0 ? q : k);
    const float* src = base + ((size_t)h * LL + (size_t)m * 64) * DD + d;
    float s = 0.f;
#pragma unroll 8
    for (int r = 0; r < 64; ++r) s += src[r * DD];
    s *= (1.f / 64.f);
    if (blockIdx.z == 0)
        g_qpool[(h * MB + m) * DD + d] = s;
    else
        g_kpool[(h * NBLK + m) * DD + d] = s - g_kmean[h * DD + d];
}

// ---------- Kernel C: block scores + top-16 LUT ----------
__global__ void lut_kernel() {
    __shared__ float qrow[64];
    __shared__ float kp[128 * 65];
    __shared__ float sc[128];
    const int m = blockIdx.x, h = blockIdx.y, t = threadIdx.x;

    if (t < 64) qrow[t] = g_qpool[(h * MB + m) * DD + t];
    for (int i = t; i < 128 * 64; i += 128) {
        int n = i >> 6, d = i & 63;
        kp[n * 65 + d] = g_kpool[(h * NBLK + n) * DD + d];
    }
    __syncthreads();

    float acc = 0.f;
#pragma unroll 8
    for (int d = 0; d < 64; ++d) acc += qrow[d] * kp[t * 65 + d];
    sc[t] = acc;
    __syncthreads();

    if (t < 32) {
        for (int r = 0; r < TSEL; ++r) {
            float bv = -CUDART_INF_F;
            int bi = 0;
#pragma unroll
            for (int kk = 0; kk < 4; ++kk) {
                int n = t + 32 * kk;
                float v = sc[n];
                if (v > bv || (v == bv && n < bi)) { bv = v; bi = n; }
            }
#pragma unroll
            for (int s = 16; s > 0; s >>= 1) {
                float ov = __shfl_xor_sync(0xffffffffu, bv, s);
                int   oi = __shfl_xor_sync(0xffffffffu, bi, s);
                if (ov > bv || (ov == bv && oi < bi)) { bv = ov; bi = oi; }
            }
            if (t == 0) {
                g_lut[(h * MB + m) * TSEL + r] = bi;
                sc[bi] = -CUDART_INF_F;
            }
            __syncwarp();
        }
    }
}

// ---------- Kernel D: sparse attention (v6: mma.sync bf16 hi/lo, reg-resident softmax) ----------
// smem: Khi[128][128B] | Klo | Vhi | Vlo  (bf16, chunk^(kv&7) 16B swizzle) | lut
#define OFF_KHI 0
#define OFF_KLO 16384
#define OFF_VHI 32768
#define OFF_VLO 49152
#define OFF_LUT 65536
#define SMEM_BYTES (65536 + 64)

__global__ void __launch_bounds__(128, 2)
attn_kernel(const float* __restrict__ q, const float* __restrict__ k,
            const float* __restrict__ v, float* __restrict__ out) {
    extern __shared__ char sb[];
    const uint32_t sbu = smem_to_u32(sb);
    int* LUTs = (int*)(sb + OFF_LUT);

    const int m = blockIdx.x;
    const int h = blockIdx.y;
    const int tid = threadIdx.x;
    const int lane = tid & 31;
    const int w = tid >> 5;
    const int g = lane >> 2;     // fragment row group 0..7
    const int t4 = lane & 3;     // fragment col/k group 0..3
    const int isel = lane & 7;   // ldmatrix row within 8x8
    const int gsel = lane >> 3;  // ldmatrix matrix group 0..3

    if (tid < TSEL) LUTs[tid] = g_lut[(h * MB + m) * TSEL + tid];

    // ---- Q fragments (A of S), scaled 0.125, hi/lo split, built once from gmem ----
    unsigned qhi[4][4], qlo[4][4];
    {
        const float* qb = q + ((size_t)h * LL + (size_t)m * 64) * DD;
        const int r0 = 16 * w + g;
#pragma unroll
        for (int kt = 0; kt < 4; ++kt) {
            const int d0 = 16 * kt + 2 * t4;
            float2 x00 = *(const float2*)(qb + (size_t)r0 * DD + d0);
            float2 x10 = *(const float2*)(qb + (size_t)(r0 + 8) * DD + d0);
            float2 x01 = *(const float2*)(qb + (size_t)r0 * DD + d0 + 8);
            float2 x11 = *(const float2*)(qb + (size_t)(r0 + 8) * DD + d0 + 8);
            packsplit(x00.x * 0.125f, x00.y * 0.125f, qhi[kt][0], qlo[kt][0]);
            packsplit(x10.x * 0.125f, x10.y * 0.125f, qhi[kt][1], qlo[kt][1]);
            packsplit(x01.x * 0.125f, x01.y * 0.125f, qhi[kt][2], qlo[kt][2]);
            packsplit(x11.x * 0.125f, x11.y * 0.125f, qhi[kt][3], qlo[kt][3]);
        }
    }

    float mrow0 = -CUDART_INF_F, mrow1 = -CUDART_INF_F;
    float lrow0 = 0.f, lrow1 = 0.f;
    float O[8][4];
#pragma unroll
    for (int nt = 0; nt < 8; ++nt) { O[nt][0] = 0.f; O[nt][1] = 0.f; O[nt][2] = 0.f; O[nt][3] = 0.f; }

    const float* kg = k + (size_t)h * LL * DD;
    const float* vg = v + (size_t)h * LL * DD;
    const int gr = 32 * w + lane;  // this thread's kv row (0..127)

    // precomputed ldmatrix lane-offsets
    const int s_row_off = 8 * (gsel >> 1) + isel;  // S: b0/b1 tiles share rows per nt
    const int s_par = gsel & 1;
    const int v_row_add = 8 * (gsel & 1) + isel;   // PV(trans): b0 rows +0, b1 rows +8
    const int v_nt_add = gsel >> 1;

    for (int bt = 0; bt < 8; ++bt) {
        __syncthreads();  // prev iter's LDSM reads done; LUT visible (iter 0)

        // ---- convert K,V (2 blocks = 128 kv rows) to bf16 hi/lo in smem ----
        {
            const int nb = LUTs[2 * bt + (gr >> 6)];
            const float4* kr = (const float4*)(kg + ((size_t)nb * 64 + (gr & 63)) * DD);
            const float4* vr = (const float4*)(vg + ((size_t)nb * 64 + (gr & 63)) * DD);
            char* khd = sb + OFF_KHI + gr * 128;
            char* kld = sb + OFF_KLO + gr * 128;
            char* vhd = sb + OFF_VHI + gr * 128;
            char* vld = sb + OFF_VLO + gr * 128;
#pragma unroll
            for (int c = 0; c < 8; ++c) {
                const int pc = ((c ^ (lane & 7)) << 4);
                uint4 hi, lo;
                cvt8(kr[2 * c], kr[2 * c + 1], hi, lo);
                *(uint4*)(khd + pc) = hi;
                *(uint4*)(kld + pc) = lo;
                cvt8(vr[2 * c], vr[2 * c + 1], hi, lo);
                *(uint4*)(vhd + pc) = hi;
                *(uint4*)(vld + pc) = lo;
            }
        }
        __syncthreads();

        // ---- S = Q @ K^T (16q x 128kv per warp), 3-term bf16 split ----
        float sacc[16][4];
#pragma unroll
        for (int nt = 0; nt < 16; ++nt) {
            sacc[nt][0] = 0.f; sacc[nt][1] = 0.f; sacc[nt][2] = 0.f; sacc[nt][3] = 0.f;
        }
#pragma unroll
        for (int np = 0; np < 8; ++np) {
#pragma unroll
            for (int kt = 0; kt < 4; ++kt) {
                const uint32_t off =
                    (uint32_t)(16 * np + s_row_off) * 128 + (((2 * kt + s_par) ^ isel) << 4);
                unsigned bh0, bh1, bh2, bh3, bl0, bl1, bl2, bl3;
                ldsm_x4(bh0, bh1, bh2, bh3, sbu + OFF_KHI + off);
                ldsm_x4(bl0, bl1, bl2, bl3, sbu + OFF_KLO + off);
                mma_bf16(sacc[2 * np], qhi[kt], bh0, bh1);
                mma_bf16(sacc[2 * np], qlo[kt], bh0, bh1);
                mma_bf16(sacc[2 * np], qhi[kt], bl0, bl1);
                mma_bf16(sacc[2 * np + 1], qhi[kt], bh2, bh3);
                mma_bf16(sacc[2 * np + 1], qlo[kt], bh2, bh3);
                mma_bf16(sacc[2 * np + 1], qhi[kt], bl2, bl3);
            }
        }

        // ---- online softmax: rows r0=16w+g (c0,c1), r1=r0+8 (c2,c3); quad reduce ----
        float mx0 = sacc[0][0], mx1 = sacc[0][2];
#pragma unroll
        for (int nt = 0; nt < 16; ++nt) {
            mx0 = fmaxf(mx0, fmaxf(sacc[nt][0], sacc[nt][1]));
            mx1 = fmaxf(mx1, fmaxf(sacc[nt][2], sacc[nt][3]));
        }
        mx0 = fmaxf(mx0, __shfl_xor_sync(0xffffffffu, mx0, 1));
        mx0 = fmaxf(mx0, __shfl_xor_sync(0xffffffffu, mx0, 2));
        mx1 = fmaxf(mx1, __shfl_xor_sync(0xffffffffu, mx1, 1));
        mx1 = fmaxf(mx1, __shfl_xor_sync(0xffffffffu, mx1, 2));
        const float mn0 = fmaxf(mrow0, mx0), mn1 = fmaxf(mrow1, mx1);
        const float al0 = __expf(mrow0 - mn0), al1 = __expf(mrow1 - mn1);
        mrow0 = mn0; mrow1 = mn1;
        float sum0 = 0.f, sum1 = 0.f;
#pragma unroll
        for (int nt = 0; nt < 16; ++nt) {
            float p0 = __expf(sacc[nt][0] - mn0);
            float p1 = __expf(sacc[nt][1] - mn0);
            float p2 = __expf(sacc[nt][2] - mn1);
            float p3 = __expf(sacc[nt][3] - mn1);
            sacc[nt][0] = p0; sacc[nt][1] = p1; sacc[nt][2] = p2; sacc[nt][3] = p3;
            sum0 += p0 + p1;
            sum1 += p2 + p3;
        }
        sum0 += __shfl_xor_sync(0xffffffffu, sum0, 1);
        sum0 += __shfl_xor_sync(0xffffffffu, sum0, 2);
        sum1 += __shfl_xor_sync(0xffffffffu, sum1, 1);
        sum1 += __shfl_xor_sync(0xffffffffu, sum1, 2);
        lrow0 = lrow0 * al0 + sum0;
        lrow1 = lrow1 * al1 + sum1;
#pragma unroll
        for (int nt = 0; nt < 8; ++nt) {
            O[nt][0] *= al0; O[nt][1] *= al0; O[nt][2] *= al1; O[nt][3] *= al1;
        }

        // ---- repack P (C-frags) into A-frags, bf16 hi/lo ----
        unsigned phi[8][4], plo[8][4];
#pragma unroll
        for (int jj = 0; jj < 8; ++jj) {
            packsplit(sacc[2 * jj][0], sacc[2 * jj][1], phi[jj][0], plo[jj][0]);
            packsplit(sacc[2 * jj][2], sacc[2 * jj][3], phi[jj][1], plo[jj][1]);
            packsplit(sacc[2 * jj + 1][0], sacc[2 * jj + 1][1], phi[jj][2], plo[jj][2]);
            packsplit(sacc[2 * jj + 1][2], sacc[2 * jj + 1][3], phi[jj][3], plo[jj][3]);
        }

        // ---- O += P @ V, 3-term split, ldmatrix.trans B-frags ----
#pragma unroll
        for (int kt = 0; kt < 8; ++kt) {
#pragma unroll
            for (int np = 0; np < 4; ++np) {
                const uint32_t off =
                    (uint32_t)(16 * kt + v_row_add) * 128 + (((2 * np + v_nt_add) ^ isel) << 4);
                unsigned vh0, vh1, vh2, vh3, vl0, vl1, vl2, vl3;
                ldsm_x4t(vh0, vh1, vh2, vh3, sbu + OFF_VHI + off);
                ldsm_x4t(vl0, vl1, vl2, vl3, sbu + OFF_VLO + off);
                mma_bf16(O[2 * np], phi[kt], vh0, vh1);
                mma_bf16(O[2 * np], plo[kt], vh0, vh1);
                mma_bf16(O[2 * np], phi[kt], vl0, vl1);
                mma_bf16(O[2 * np + 1], phi[kt], vh2, vh3);
                mma_bf16(O[2 * np + 1], plo[kt], vh2, vh3);
                mma_bf16(O[2 * np + 1], phi[kt], vl2, vl3);
            }
        }
    }

    // ---- normalize + write ----
    {
        float* og = out + ((size_t)h * LL + (size_t)m * 64) * DD;
        const float inv0 = 1.0f / lrow0, inv1 = 1.0f / lrow1;
        const int r0 = 16 * w + g;
#pragma unroll
        for (int nt = 0; nt < 8; ++nt) {
            *(float2*)(og + (size_t)r0 * DD + 8 * nt + 2 * t4) =
                make_float2(O[nt][0] * inv0, O[nt][1] * inv0);
            *(float2*)(og + (size_t)(r0 + 8) * DD + 8 * nt + 2 * t4) =
                make_float2(O[nt][2] * inv1, O[nt][3] * inv1);
        }
    }
}

extern "C" void kernel_launch(void* const* d_in, const int* in_sizes, int n_in,
                              void* d_out, int out_size) {
    const float* q = (const float*)d_in[0];
    const float* k = (const float*)d_in[1];
    const float* v = (const float*)d_in[2];
    float* out = (float*)d_out;

    cudaFuncSetAttribute(attn_kernel, cudaFuncAttributeMaxDynamicSharedMemorySize, SMEM_BYTES);

    kmean1_kernel<<<dim3(HH, 32), 256>>>(k);
    kmean2_kernel<<<HH, 64>>>();
    pool_kernel<<<dim3(MB, HH, 2), 64>>>(q, k);
    lut_kernel<<<dim3(MB, HH), 128>>>();
    attn_kernel<<<dim3(MB, HH), 128, SMEM_BYTES>>>(q, k, v, out);
}

// round 14
// speedup vs baseline: 2.5710x; 1.0176x over previous
#include <cuda_runtime.h>
#include <cuda_bf16.h>
#include <math_constants.h>
#include <cstdint>

#define HH   16
#define LL   8192
#define DD   64
#define MB   128
#define NBLK 128
#define TSEL 16

// scratch (no allocation allowed -> device globals)
__device__ float g_kpart[HH * 32 * DD];
__device__ float g_kmean[HH * DD];
__device__ float g_qpool[HH * MB * DD];
__device__ float g_kpool[HH * NBLK * DD];
__device__ int   g_lut[HH * MB * TSEL];

// ---------- helpers ----------
static __device__ __forceinline__ uint32_t smem_to_u32(const void* p) {
    uint32_t a;
    asm("{ .reg .u64 t; cvta.to.shared.u64 t, %1; cvt.u32.u64 %0, t; }" : "=r"(a) : "l"(p));
    return a;
}
static __device__ __forceinline__ unsigned pkbf2(float a, float b) {
    __nv_bfloat162 t = __floats2bfloat162_rn(a, b);
    return *reinterpret_cast<unsigned*>(&t);
}
static __device__ __forceinline__ void split1(float x, float& hi, float& lo) {
    __nv_bfloat16 hh = __float2bfloat16(x);
    hi = __bfloat162float(hh);
    lo = x - hi;
}
static __device__ __forceinline__ void packsplit(float a, float b, unsigned& hi, unsigned& lo) {
    float ha, la, hb, lb;
    split1(a, ha, la);
    split1(b, hb, lb);
    hi = pkbf2(ha, hb);
    lo = pkbf2(la, lb);
}
// bf16 mma m16n8k16, D = A*B + D (fp32 accum)
static __device__ __forceinline__ void mma_bf16(float* c, const unsigned* a, unsigned b0, unsigned b1) {
    asm volatile(
        "mma.sync.aligned.m16n8k16.row.col.f32.bf16.bf16.f32 "
        "{%0,%1,%2,%3}, {%4,%5,%6,%7}, {%8,%9}, {%0,%1,%2,%3};"
        : "+f"(c[0]), "+f"(c[1]), "+f"(c[2]), "+f"(c[3])
        : "r"(a[0]), "r"(a[1]), "r"(a[2]), "r"(a[3]), "r"(b0), "r"(b1));
}
static __device__ __forceinline__ void ldsm_x4(unsigned& r0, unsigned& r1, unsigned& r2, unsigned& r3,
                                               uint32_t addr) {
    asm volatile("ldmatrix.sync.aligned.m8n8.x4.shared.b16 {%0,%1,%2,%3}, [%4];"
                 : "=r"(r0), "=r"(r1), "=r"(r2), "=r"(r3) : "r"(addr));
}
static __device__ __forceinline__ void ldsm_x4t(unsigned& r0, unsigned& r1, unsigned& r2, unsigned& r3,
                                                uint32_t addr) {
    asm volatile("ldmatrix.sync.aligned.m8n8.x4.trans.shared.b16 {%0,%1,%2,%3}, [%4];"
                 : "=r"(r0), "=r"(r1), "=r"(r2), "=r"(r3) : "r"(addr));
}
// convert 8 floats -> bf16 hi/lo uint4 pair
static __device__ __forceinline__ void cvt8(const float4 f0, const float4 f1, uint4& hi, uint4& lo) {
    float h0, l0, h1, l1, h2, l2, h3, l3, h4, l4, h5, l5, h6, l6, h7, l7;
    split1(f0.x, h0, l0); split1(f0.y, h1, l1); split1(f0.z, h2, l2); split1(f0.w, h3, l3);
    split1(f1.x, h4, l4); split1(f1.y, h5, l5); split1(f1.z, h6, l6); split1(f1.w, h7, l7);
    hi = make_uint4(pkbf2(h0, h1), pkbf2(h2, h3), pkbf2(h4, h5), pkbf2(h6, h7));
    lo = make_uint4(pkbf2(l0, l1), pkbf2(l2, l3), pkbf2(l4, l5), pkbf2(l6, l7));
}

// ---------- Kernel A1: partial k sums ----------
__global__ void kmean1_kernel(const float* __restrict__ k) {
    __shared__ float red[256];
    const int h = blockIdx.x, seg = blockIdx.y, t = threadIdx.x;
    const int d = t & 63, g = t >> 6;
    const float* src = k + ((size_t)h * LL + (size_t)seg * 256 + (size_t)g * 64) * DD + d;
    float s = 0.f;
#pragma unroll 8
    for (int r = 0; r < 64; ++r) s += src[(size_t)r * DD];
    red[t] = s;
    __syncthreads();
    if (t < 64)
        g_kpart[(h * 32 + seg) * DD + t] = red[t] + red[t + 64] + red[t + 128] + red[t + 192];
}

// ---------- Kernel A2: combine partials ----------
__global__ void kmean2_kernel() {
    const int h = blockIdx.x, d = threadIdx.x;
    float tot = 0.f;
#pragma unroll
    for (int s = 0; s < 32; ++s) tot += g_kpart[(h * 32 + s) * DD + d];
    g_kmean[h * DD + d] = tot * (1.f / 8192.f);
}

// ---------- Kernel B: block pools ----------
__global__ void pool_kernel(const float* __restrict__ q, const float* __restrict__ k) {
    const int m = blockIdx.x, h = blockIdx.y, d = threadIdx.x;
    const float* base = (blockIdx.z == 0 ? q : k);
    const float* src = base + ((size_t)h * LL + (size_t)m * 64) * DD + d;
    float s = 0.f;
#pragma unroll 8
    for (int r = 0; r < 64; ++r) s += src[r * DD];
    s *= (1.f / 64.f);
    if (blockIdx.z == 0)
        g_qpool[(h * MB + m) * DD + d] = s;
    else
        g_kpool[(h * NBLK + m) * DD + d] = s - g_kmean[h * DD + d];
}

// ---------- Kernel C: block scores + top-16 LUT ----------
__global__ void lut_kernel() {
    __shared__ float qrow[64];
    __shared__ float kp[128 * 65];
    __shared__ float sc[128];
    const int m = blockIdx.x, h = blockIdx.y, t = threadIdx.x;

    if (t < 64) qrow[t] = g_qpool[(h * MB + m) * DD + t];
    for (int i = t; i < 128 * 64; i += 128) {
        int n = i >> 6, d = i & 63;
        kp[n * 65 + d] = g_kpool[(h * NBLK + n) * DD + d];
    }
    __syncthreads();

    float acc = 0.f;
#pragma unroll 8
    for (int d = 0; d < 64; ++d) acc += qrow[d] * kp[t * 65 + d];
    sc[t] = acc;
    __syncthreads();

    if (t < 32) {
        for (int r = 0; r < TSEL; ++r) {
            float bv = -CUDART_INF_F;
            int bi = 0;
#pragma unroll
            for (int kk = 0; kk < 4; ++kk) {
                int n = t + 32 * kk;
                float v = sc[n];
                if (v > bv || (v == bv && n < bi)) { bv = v; bi = n; }
            }
#pragma unroll
            for (int s = 16; s > 0; s >>= 1) {
                float ov = __shfl_xor_sync(0xffffffffu, bv, s);
                int   oi = __shfl_xor_sync(0xffffffffu, bi, s);
                if (ov > bv || (ov == bv && oi < bi)) { bv = ov; bi = oi; }
            }
            if (t == 0) {
                g_lut[(h * MB + m) * TSEL + r] = bi;
                sc[bi] = -CUDART_INF_F;
            }
            __syncwarp();
        }
    }
}

// ---------- Kernel D: sparse attention (v7: warp-specialized double-buffered HMMA) ----------
// smem: 2 buffers x { Khi[128][128B] | Klo | Vhi | Vlo } (chunk^(kv&7) 16B swizzle) | lut
#define BUF_BYTES 65536
#define OFF_KHI 0
#define OFF_KLO 16384
#define OFF_VHI 32768
#define OFF_VLO 49152
#define OFF_LUT (2 * BUF_BYTES)
#define SMEM_BYTES (2 * BUF_BYTES + 64)

__global__ void __launch_bounds__(256, 1)
attn_kernel(const float* __restrict__ q, const float* __restrict__ k,
            const float* __restrict__ v, float* __restrict__ out) {
    extern __shared__ char sb[];
    const uint32_t sbu = smem_to_u32(sb);
    int* LUTs = (int*)(sb + OFF_LUT);

    const int m = blockIdx.x;
    const int h = blockIdx.y;
    const int tid = threadIdx.x;
    const bool isProd = (tid >= 128);

    if (tid < TSEL) LUTs[tid] = g_lut[(h * MB + m) * TSEL + tid];
    __syncthreads();  // LUT visible to producers

    const float* kg = k + (size_t)h * LL * DD;
    const float* vg = v + (size_t)h * LL * DD;

    if (isProd) {
        // ================= PRODUCER: warps 4-7, one kv row each =================
        const int pid = tid - 128;          // 0..127 = kv row
        const int sw7 = pid & 7;
        char* khd_base = sb + OFF_KHI + pid * 128;
        // fill buffer for iteration bt into buf[bt&1]
        for (int bt = 0; bt < 8; ++bt) {
            {
                const int nb = LUTs[2 * bt + (pid >> 6)];
                const float4* kr = (const float4*)(kg + ((size_t)nb * 64 + (pid & 63)) * DD);
                const float4* vr = (const float4*)(vg + ((size_t)nb * 64 + (pid & 63)) * DD);
                char* base = khd_base + (bt & 1) * BUF_BYTES;
#pragma unroll
                for (int c = 0; c < 8; ++c) {
                    const int pc = ((c ^ sw7) << 4);
                    uint4 hi, lo;
                    cvt8(kr[2 * c], kr[2 * c + 1], hi, lo);
                    *(uint4*)(base + pc) = hi;
                    *(uint4*)(base + (OFF_KLO - OFF_KHI) + pc) = lo;
                    cvt8(vr[2 * c], vr[2 * c + 1], hi, lo);
                    *(uint4*)(base + (OFF_VHI - OFF_KHI) + pc) = hi;
                    *(uint4*)(base + (OFF_VLO - OFF_KHI) + pc) = lo;
                }
            }
            __syncthreads();  // publish buf[bt&1]; consumer is one iter behind
        }
        // consumer still working on iteration 7; it has no more barriers to hit
        return;
    }

    // ================= CONSUMER: warps 0-3, 16 q rows each =================
    const int lane = tid & 31;
    const int w = tid >> 5;
    const int g = lane >> 2;
    const int t4 = lane & 3;
    const int isel = lane & 7;
    const int gsel = lane >> 3;

    // Q fragments (A of S), scaled 0.125, hi/lo split (overlaps producer's first fill)
    unsigned qhi[4][4], qlo[4][4];
    {
        const float* qb = q + ((size_t)h * LL + (size_t)m * 64) * DD;
        const int r0 = 16 * w + g;
#pragma unroll
        for (int kt = 0; kt < 4; ++kt) {
            const int d0 = 16 * kt + 2 * t4;
            float2 x00 = *(const float2*)(qb + (size_t)r0 * DD + d0);
            float2 x10 = *(const float2*)(qb + (size_t)(r0 + 8) * DD + d0);
            float2 x01 = *(const float2*)(qb + (size_t)r0 * DD + d0 + 8);
            float2 x11 = *(const float2*)(qb + (size_t)(r0 + 8) * DD + d0 + 8);
            packsplit(x00.x * 0.125f, x00.y * 0.125f, qhi[kt][0], qlo[kt][0]);
            packsplit(x10.x * 0.125f, x10.y * 0.125f, qhi[kt][1], qlo[kt][1]);
            packsplit(x01.x * 0.125f, x01.y * 0.125f, qhi[kt][2], qlo[kt][2]);
            packsplit(x11.x * 0.125f, x11.y * 0.125f, qhi[kt][3], qlo[kt][3]);
        }
    }

    float mrow0 = -CUDART_INF_F, mrow1 = -CUDART_INF_F;
    float lrow0 = 0.f, lrow1 = 0.f;
    float O[8][4];
#pragma unroll
    for (int nt = 0; nt < 8; ++nt) { O[nt][0] = 0.f; O[nt][1] = 0.f; O[nt][2] = 0.f; O[nt][3] = 0.f; }

    const int s_row_off = 8 * (gsel >> 1) + isel;
    const int s_par = gsel & 1;
    const int v_row_add = 8 * (gsel & 1) + isel;
    const int v_nt_add = gsel >> 1;

    for (int bt = 0; bt < 8; ++bt) {
        __syncthreads();  // wait: producer published buf[bt&1]; also frees buf[(bt+1)&1]
        const uint32_t bufb = sbu + (bt & 1) * BUF_BYTES;

        // ---- S = Q @ K^T (16q x 128kv per warp), 3-term bf16 split ----
        float sacc[16][4];
#pragma unroll
        for (int nt = 0; nt < 16; ++nt) {
            sacc[nt][0] = 0.f; sacc[nt][1] = 0.f; sacc[nt][2] = 0.f; sacc[nt][3] = 0.f;
        }
#pragma unroll
        for (int np = 0; np < 8; ++np) {
#pragma unroll
            for (int kt = 0; kt < 4; ++kt) {
                const uint32_t off =
                    (uint32_t)(16 * np + s_row_off) * 128 + (((2 * kt + s_par) ^ isel) << 4);
                unsigned bh0, bh1, bh2, bh3, bl0, bl1, bl2, bl3;
                ldsm_x4(bh0, bh1, bh2, bh3, bufb + OFF_KHI + off);
                ldsm_x4(bl0, bl1, bl2, bl3, bufb + OFF_KLO + off);
                mma_bf16(sacc[2 * np], qhi[kt], bh0, bh1);
                mma_bf16(sacc[2 * np], qlo[kt], bh0, bh1);
                mma_bf16(sacc[2 * np], qhi[kt], bl0, bl1);
                mma_bf16(sacc[2 * np + 1], qhi[kt], bh2, bh3);
                mma_bf16(sacc[2 * np + 1], qlo[kt], bh2, bh3);
                mma_bf16(sacc[2 * np + 1], qhi[kt], bl2, bl3);
            }
        }

        // ---- online softmax: quad-lane reduce (rows r0: c0,c1; r0+8: c2,c3) ----
        float mx0 = sacc[0][0], mx1 = sacc[0][2];
#pragma unroll
        for (int nt = 0; nt < 16; ++nt) {
            mx0 = fmaxf(mx0, fmaxf(sacc[nt][0], sacc[nt][1]));
            mx1 = fmaxf(mx1, fmaxf(sacc[nt][2], sacc[nt][3]));
        }
        mx0 = fmaxf(mx0, __shfl_xor_sync(0xffffffffu, mx0, 1));
        mx0 = fmaxf(mx0, __shfl_xor_sync(0xffffffffu, mx0, 2));
        mx1 = fmaxf(mx1, __shfl_xor_sync(0xffffffffu, mx1, 1));
        mx1 = fmaxf(mx1, __shfl_xor_sync(0xffffffffu, mx1, 2));
        const float mn0 = fmaxf(mrow0, mx0), mn1 = fmaxf(mrow1, mx1);
        const float al0 = __expf(mrow0 - mn0), al1 = __expf(mrow1 - mn1);
        mrow0 = mn0; mrow1 = mn1;
        float sum0 = 0.f, sum1 = 0.f;
#pragma unroll
        for (int nt = 0; nt < 16; ++nt) {
            float p0 = __expf(sacc[nt][0] - mn0);
            float p1 = __expf(sacc[nt][1] - mn0);
            float p2 = __expf(sacc[nt][2] - mn1);
            float p3 = __expf(sacc[nt][3] - mn1);
            sacc[nt][0] = p0; sacc[nt][1] = p1; sacc[nt][2] = p2; sacc[nt][3] = p3;
            sum0 += p0 + p1;
            sum1 += p2 + p3;
        }
        sum0 += __shfl_xor_sync(0xffffffffu, sum0, 1);
        sum0 += __shfl_xor_sync(0xffffffffu, sum0, 2);
        sum1 += __shfl_xor_sync(0xffffffffu, sum1, 1);
        sum1 += __shfl_xor_sync(0xffffffffu, sum1, 2);
        lrow0 = lrow0 * al0 + sum0;
        lrow1 = lrow1 * al1 + sum1;
#pragma unroll
        for (int nt = 0; nt < 8; ++nt) {
            O[nt][0] *= al0; O[nt][1] *= al0; O[nt][2] *= al1; O[nt][3] *= al1;
        }

        // ---- repack P (C-frags) into A-frags, bf16 hi/lo ----
        unsigned phi[8][4], plo[8][4];
#pragma unroll
        for (int jj = 0; jj < 8; ++jj) {
            packsplit(sacc[2 * jj][0], sacc[2 * jj][1], phi[jj][0], plo[jj][0]);
            packsplit(sacc[2 * jj][2], sacc[2 * jj][3], phi[jj][1], plo[jj][1]);
            packsplit(sacc[2 * jj + 1][0], sacc[2 * jj + 1][1], phi[jj][2], plo[jj][2]);
            packsplit(sacc[2 * jj + 1][2], sacc[2 * jj + 1][3], phi[jj][3], plo[jj][3]);
        }

        // ---- O += P @ V, 3-term split, ldmatrix.trans B-frags ----
#pragma unroll
        for (int kt = 0; kt < 8; ++kt) {
#pragma unroll
            for (int np = 0; np < 4; ++np) {
                const uint32_t off =
                    (uint32_t)(16 * kt + v_row_add) * 128 + (((2 * np + v_nt_add) ^ isel) << 4);
                unsigned vh0, vh1, vh2, vh3, vl0, vl1, vl2, vl3;
                ldsm_x4t(vh0, vh1, vh2, vh3, bufb + OFF_VHI + off);
                ldsm_x4t(vl0, vl1, vl2, vl3, bufb + OFF_VLO + off);
                mma_bf16(O[2 * np], phi[kt], vh0, vh1);
                mma_bf16(O[2 * np], plo[kt], vh0, vh1);
                mma_bf16(O[2 * np], phi[kt], vl0, vl1);
                mma_bf16(O[2 * np + 1], phi[kt], vh2, vh3);
                mma_bf16(O[2 * np + 1], plo[kt], vh2, vh3);
                mma_bf16(O[2 * np + 1], phi[kt], vl2, vl3);
            }
        }
    }

    // ---- normalize + write ----
    {
        float* og = out + ((size_t)h * LL + (size_t)m * 64) * DD;
        const float inv0 = 1.0f / lrow0, inv1 = 1.0f / lrow1;
        const int r0 = 16 * w + g;
#pragma unroll
        for (int nt = 0; nt < 8; ++nt) {
            *(float2*)(og + (size_t)r0 * DD + 8 * nt + 2 * t4) =
                make_float2(O[nt][0] * inv0, O[nt][1] * inv0);
            *(float2*)(og + (size_t)(r0 + 8) * DD + 8 * nt + 2 * t4) =
                make_float2(O[nt][2] * inv1, O[nt][3] * inv1);
        }
    }
}

extern "C" void kernel_launch(void* const* d_in, const int* in_sizes, int n_in,
                              void* d_out, int out_size) {
    const float* q = (const float*)d_in[0];
    const float* k = (const float*)d_in[1];
    const float* v = (const float*)d_in[2];
    float* out = (float*)d_out;

    cudaFuncSetAttribute(attn_kernel, cudaFuncAttributeMaxDynamicSharedMemorySize, SMEM_BYTES);

    kmean1_kernel<<<dim3(HH, 32), 256>>>(k);
    kmean2_kernel<<<HH, 64>>>();
    pool_kernel<<<dim3(MB, HH, 2), 64>>>(q, k);
    lut_kernel<<<dim3(MB, HH), 128>>>();
    attn_kernel<<<dim3(MB, HH), 256, SMEM_BYTES>>>(q, k, v, out);
}

// round 15
// speedup vs baseline: 3.1085x; 1.2091x over previous
#include <cuda_runtime.h>
#include <cuda_fp16.h>
#include <math_constants.h>
#include <cstdint>

#define HH   16
#define LL   8192
#define DD   64
#define MB   128
#define NBLK 128
#define TSEL 16

// scratch (no allocation allowed -> device globals)
__device__ float g_kpart[HH * 32 * DD];
__device__ float g_kmean[HH * DD];
__device__ float g_qpool[HH * MB * DD];
__device__ float g_kpool[HH * NBLK * DD];
__device__ int   g_lut[HH * MB * TSEL];

// ---------- helpers ----------
static __device__ __forceinline__ uint32_t smem_to_u32(const void* p) {
    uint32_t a;
    asm("{ .reg .u64 t; cvta.to.shared.u64 t, %1; cvt.u32.u64 %0, t; }" : "=r"(a) : "l"(p));
    return a;
}
static __device__ __forceinline__ unsigned pkh2(float a, float b) {
    __half2 t = __floats2half2_rn(a, b);
    return *reinterpret_cast<unsigned*>(&t);
}
static __device__ __forceinline__ void split1(float x, float& hi, float& lo) {
    __half hh = __float2half_rn(x);
    hi = __half2float(hh);
    lo = x - hi;
}
static __device__ __forceinline__ void packsplit(float a, float b, unsigned& hi, unsigned& lo) {
    float ha, la, hb, lb;
    split1(a, ha, la);
    split1(b, hb, lb);
    hi = pkh2(ha, hb);
    lo = pkh2(la, lb);
}
// fp16 mma m16n8k16, D = A*B + D (fp32 accum)
static __device__ __forceinline__ void mma_f16(float* c, const unsigned* a, unsigned b0, unsigned b1) {
    asm volatile(
        "mma.sync.aligned.m16n8k16.row.col.f32.f16.f16.f32 "
        "{%0,%1,%2,%3}, {%4,%5,%6,%7}, {%8,%9}, {%0,%1,%2,%3};"
        : "+f"(c[0]), "+f"(c[1]), "+f"(c[2]), "+f"(c[3])
        : "r"(a[0]), "r"(a[1]), "r"(a[2]), "r"(a[3]), "r"(b0), "r"(b1));
}
static __device__ __forceinline__ void ldsm_x4(unsigned& r0, unsigned& r1, unsigned& r2, unsigned& r3,
                                               uint32_t addr) {
    asm volatile("ldmatrix.sync.aligned.m8n8.x4.shared.b16 {%0,%1,%2,%3}, [%4];"
                 : "=r"(r0), "=r"(r1), "=r"(r2), "=r"(r3) : "r"(addr));
}
static __device__ __forceinline__ void ldsm_x4t(unsigned& r0, unsigned& r1, unsigned& r2, unsigned& r3,
                                                uint32_t addr) {
    asm volatile("ldmatrix.sync.aligned.m8n8.x4.trans.shared.b16 {%0,%1,%2,%3}, [%4];"
                 : "=r"(r0), "=r"(r1), "=r"(r2), "=r"(r3) : "r"(addr));
}
// convert 8 floats -> fp16 uint4 (hi only)
static __device__ __forceinline__ uint4 cvt8h(const float4 f0, const float4 f1) {
    return make_uint4(pkh2(f0.x, f0.y), pkh2(f0.z, f0.w), pkh2(f1.x, f1.y), pkh2(f1.z, f1.w));
}

// ---------- Kernel A1: partial k sums ----------
__global__ void kmean1_kernel(const float* __restrict__ k) {
    __shared__ float red[256];
    const int h = blockIdx.x, seg = blockIdx.y, t = threadIdx.x;
    const int d = t & 63, g = t >> 6;
    const float* src = k + ((size_t)h * LL + (size_t)seg * 256 + (size_t)g * 64) * DD + d;
    float s = 0.f;
#pragma unroll 8
    for (int r = 0; r < 64; ++r) s += src[(size_t)r * DD];
    red[t] = s;
    __syncthreads();
    if (t < 64)
        g_kpart[(h * 32 + seg) * DD + t] = red[t] + red[t + 64] + red[t + 128] + red[t + 192];
}

// ---------- Kernel A2: combine partials ----------
__global__ void kmean2_kernel() {
    const int h = blockIdx.x, d = threadIdx.x;
    float tot = 0.f;
#pragma unroll
    for (int s = 0; s < 32; ++s) tot += g_kpart[(h * 32 + s) * DD + d];
    g_kmean[h * DD + d] = tot * (1.f / 8192.f);
}

// ---------- Kernel B: block pools ----------
__global__ void pool_kernel(const float* __restrict__ q, const float* __restrict__ k) {
    const int m = blockIdx.x, h = blockIdx.y, d = threadIdx.x;
    const float* base = (blockIdx.z == 0 ? q : k);
    const float* src = base + ((size_t)h * LL + (size_t)m * 64) * DD + d;
    float s = 0.f;
#pragma unroll 8
    for (int r = 0; r < 64; ++r) s += src[r * DD];
    s *= (1.f / 64.f);
    if (blockIdx.z == 0)
        g_qpool[(h * MB + m) * DD + d] = s;
    else
        g_kpool[(h * NBLK + m) * DD + d] = s - g_kmean[h * DD + d];
}

// ---------- Kernel C: block scores + top-16 LUT (8 query blocks per CTA) ----------
__global__ void lut_kernel() {
    __shared__ float qrow[64];
    __shared__ float kp[128 * 65];
    __shared__ float sc[128];
    const int m0 = blockIdx.x * 8, h = blockIdx.y, t = threadIdx.x;

    for (int i = t; i < 128 * 64; i += 128) {
        int n = i >> 6, d = i & 63;
        kp[n * 65 + d] = g_kpool[(h * NBLK + n) * DD + d];
    }

    for (int mi = 0; mi < 8; ++mi) {
        __syncthreads();  // kp ready (first) / prior sc reads done (later)
        if (t < 64) qrow[t] = g_qpool[(h * MB + m0 + mi) * DD + t];
        __syncthreads();

        float acc = 0.f;
#pragma unroll 8
        for (int d = 0; d < 64; ++d) acc += qrow[d] * kp[t * 65 + d];
        sc[t] = acc;
        __syncthreads();

        if (t < 32) {
            for (int r = 0; r < TSEL; ++r) {
                float bv = -CUDART_INF_F;
                int bi = 0;
#pragma unroll
                for (int kk = 0; kk < 4; ++kk) {
                    int n = t + 32 * kk;
                    float v = sc[n];
                    if (v > bv || (v == bv && n < bi)) { bv = v; bi = n; }
                }
#pragma unroll
                for (int s = 16; s > 0; s >>= 1) {
                    float ov = __shfl_xor_sync(0xffffffffu, bv, s);
                    int   oi = __shfl_xor_sync(0xffffffffu, bi, s);
                    if (ov > bv || (ov == bv && oi < bi)) { bv = ov; bi = oi; }
                }
                if (t == 0) {
                    g_lut[(h * MB + m0 + mi) * TSEL + r] = bi;
                    sc[bi] = -CUDART_INF_F;
                }
                __syncwarp();
            }
        }
    }
}

// ---------- Kernel D: sparse attention (v8: fp16 2-term HMMA, warp-specialized) ----------
// smem: 2 buffers x { Kh[128][128B] | Vh[128][128B] } (chunk^(kv&7) 16B swizzle) | lut
#define BUF_BYTES 32768
#define OFF_KH 0
#define OFF_VH 16384
#define OFF_LUT (2 * BUF_BYTES)
#define SMEM_BYTES (2 * BUF_BYTES + 64)

__global__ void __launch_bounds__(256, 1)
attn_kernel(const float* __restrict__ q, const float* __restrict__ k,
            const float* __restrict__ v, float* __restrict__ out) {
    extern __shared__ char sb[];
    const uint32_t sbu = smem_to_u32(sb);
    int* LUTs = (int*)(sb + OFF_LUT);

    const int m = blockIdx.x;
    const int h = blockIdx.y;
    const int tid = threadIdx.x;
    const bool isProd = (tid >= 128);

    if (tid < TSEL) LUTs[tid] = g_lut[(h * MB + m) * TSEL + tid];
    __syncthreads();  // LUT visible to producers

    const float* kg = k + (size_t)h * LL * DD;
    const float* vg = v + (size_t)h * LL * DD;

    if (isProd) {
        // ================= PRODUCER: warps 4-7, one kv row each =================
        const int pid = tid - 128;  // 0..127 = kv row
        const int sw7 = pid & 7;
        char* kbase = sb + OFF_KH + pid * 128;
        for (int bt = 0; bt < 8; ++bt) {
            const int nb = LUTs[2 * bt + (pid >> 6)];
            const float4* kr = (const float4*)(kg + ((size_t)nb * 64 + (pid & 63)) * DD);
            const float4* vr = (const float4*)(vg + ((size_t)nb * 64 + (pid & 63)) * DD);
            char* base = kbase + (bt & 1) * BUF_BYTES;
#pragma unroll
            for (int c = 0; c < 8; ++c) {
                const int pc = ((c ^ sw7) << 4);
                *(uint4*)(base + pc) = cvt8h(kr[2 * c], kr[2 * c + 1]);
                *(uint4*)(base + (OFF_VH - OFF_KH) + pc) = cvt8h(vr[2 * c], vr[2 * c + 1]);
            }
            __syncthreads();  // publish buf[bt&1]
        }
        return;
    }

    // ================= CONSUMER: warps 0-3, 16 q rows each =================
    const int lane = tid & 31;
    const int w = tid >> 5;
    const int g = lane >> 2;
    const int t4 = lane & 3;
    const int isel = lane & 7;
    const int gsel = lane >> 3;

    // Q fragments (A of S), scaled 0.125, fp16 hi/lo split (exact Q)
    unsigned qhi[4][4], qlo[4][4];
    {
        const float* qb = q + ((size_t)h * LL + (size_t)m * 64) * DD;
        const int r0 = 16 * w + g;
#pragma unroll
        for (int kt = 0; kt < 4; ++kt) {
            const int d0 = 16 * kt + 2 * t4;
            float2 x00 = *(const float2*)(qb + (size_t)r0 * DD + d0);
            float2 x10 = *(const float2*)(qb + (size_t)(r0 + 8) * DD + d0);
            float2 x01 = *(const float2*)(qb + (size_t)r0 * DD + d0 + 8);
            float2 x11 = *(const float2*)(qb + (size_t)(r0 + 8) * DD + d0 + 8);
            packsplit(x00.x * 0.125f, x00.y * 0.125f, qhi[kt][0], qlo[kt][0]);
            packsplit(x10.x * 0.125f, x10.y * 0.125f, qhi[kt][1], qlo[kt][1]);
            packsplit(x01.x * 0.125f, x01.y * 0.125f, qhi[kt][2], qlo[kt][2]);
            packsplit(x11.x * 0.125f, x11.y * 0.125f, qhi[kt][3], qlo[kt][3]);
        }
    }

    float mrow0 = -CUDART_INF_F, mrow1 = -CUDART_INF_F;
    float lrow0 = 0.f, lrow1 = 0.f;
    float O[8][4];
#pragma unroll
    for (int nt = 0; nt < 8; ++nt) { O[nt][0] = 0.f; O[nt][1] = 0.f; O[nt][2] = 0.f; O[nt][3] = 0.f; }

    const int s_row_off = 8 * (gsel >> 1) + isel;
    const int s_par = gsel & 1;
    const int v_row_add = 8 * (gsel & 1) + isel;
    const int v_nt_add = gsel >> 1;

    for (int bt = 0; bt < 8; ++bt) {
        __syncthreads();  // producer published buf[bt&1]; frees buf[(bt+1)&1]
        const uint32_t bufb = sbu + (bt & 1) * BUF_BYTES;

        // ---- S = Q @ K^T (16q x 128kv per warp), fp16 2-term ----
        float sacc[16][4];
#pragma unroll
        for (int nt = 0; nt < 16; ++nt) {
            sacc[nt][0] = 0.f; sacc[nt][1] = 0.f; sacc[nt][2] = 0.f; sacc[nt][3] = 0.f;
        }
#pragma unroll
        for (int np = 0; np < 8; ++np) {
#pragma unroll
            for (int kt = 0; kt < 4; ++kt) {
                const uint32_t off =
                    (uint32_t)(16 * np + s_row_off) * 128 + (((2 * kt + s_par) ^ isel) << 4);
                unsigned bh0, bh1, bh2, bh3;
                ldsm_x4(bh0, bh1, bh2, bh3, bufb + OFF_KH + off);
                mma_f16(sacc[2 * np], qhi[kt], bh0, bh1);
                mma_f16(sacc[2 * np], qlo[kt], bh0, bh1);
                mma_f16(sacc[2 * np + 1], qhi[kt], bh2, bh3);
                mma_f16(sacc[2 * np + 1], qlo[kt], bh2, bh3);
            }
        }

        // ---- online softmax: quad-lane reduce (rows r0: c0,c1; r0+8: c2,c3) ----
        float mx0 = sacc[0][0], mx1 = sacc[0][2];
#pragma unroll
        for (int nt = 0; nt < 16; ++nt) {
            mx0 = fmaxf(mx0, fmaxf(sacc[nt][0], sacc[nt][1]));
            mx1 = fmaxf(mx1, fmaxf(sacc[nt][2], sacc[nt][3]));
        }
        mx0 = fmaxf(mx0, __shfl_xor_sync(0xffffffffu, mx0, 1));
        mx0 = fmaxf(mx0, __shfl_xor_sync(0xffffffffu, mx0, 2));
        mx1 = fmaxf(mx1, __shfl_xor_sync(0xffffffffu, mx1, 1));
        mx1 = fmaxf(mx1, __shfl_xor_sync(0xffffffffu, mx1, 2));
        const float mn0 = fmaxf(mrow0, mx0), mn1 = fmaxf(mrow1, mx1);
        const float al0 = __expf(mrow0 - mn0), al1 = __expf(mrow1 - mn1);
        mrow0 = mn0; mrow1 = mn1;
        float sum0 = 0.f, sum1 = 0.f;
#pragma unroll
        for (int nt = 0; nt < 16; ++nt) {
            float p0 = __expf(sacc[nt][0] - mn0);
            float p1 = __expf(sacc[nt][1] - mn0);
            float p2 = __expf(sacc[nt][2] - mn1);
            float p3 = __expf(sacc[nt][3] - mn1);
            sacc[nt][0] = p0; sacc[nt][1] = p1; sacc[nt][2] = p2; sacc[nt][3] = p3;
            sum0 += p0 + p1;
            sum1 += p2 + p3;
        }
        sum0 += __shfl_xor_sync(0xffffffffu, sum0, 1);
        sum0 += __shfl_xor_sync(0xffffffffu, sum0, 2);
        sum1 += __shfl_xor_sync(0xffffffffu, sum1, 1);
        sum1 += __shfl_xor_sync(0xffffffffu, sum1, 2);
        lrow0 = lrow0 * al0 + sum0;
        lrow1 = lrow1 * al1 + sum1;
#pragma unroll
        for (int nt = 0; nt < 8; ++nt) {
            O[nt][0] *= al0; O[nt][1] *= al0; O[nt][2] *= al1; O[nt][3] *= al1;
        }

        // ---- repack P (C-frags) into A-frags, fp16 hi/lo ----
        unsigned phi[8][4], plo[8][4];
#pragma unroll
        for (int jj = 0; jj < 8; ++jj) {
            packsplit(sacc[2 * jj][0], sacc[2 * jj][1], phi[jj][0], plo[jj][0]);
            packsplit(sacc[2 * jj][2], sacc[2 * jj][3], phi[jj][1], plo[jj][1]);
            packsplit(sacc[2 * jj + 1][0], sacc[2 * jj + 1][1], phi[jj][2], plo[jj][2]);
            packsplit(sacc[2 * jj + 1][2], sacc[2 * jj + 1][3], phi[jj][3], plo[jj][3]);
        }

        // ---- O += P @ V, fp16 2-term, ldmatrix.trans B-frags ----
#pragma unroll
        for (int kt = 0; kt < 8; ++kt) {
#pragma unroll
            for (int np = 0; np < 4; ++np) {
                const uint32_t off =
                    (uint32_t)(16 * kt + v_row_add) * 128 + (((2 * np + v_nt_add) ^ isel) << 4);
                unsigned vh0, vh1, vh2, vh3;
                ldsm_x4t(vh0, vh1, vh2, vh3, bufb + OFF_VH + off);
                mma_f16(O[2 * np], phi[kt], vh0, vh1);
                mma_f16(O[2 * np], plo[kt], vh0, vh1);
                mma_f16(O[2 * np + 1], phi[kt], vh2, vh3);
                mma_f16(O[2 * np + 1], plo[kt], vh2, vh3);
            }
        }
    }

    // ---- normalize + write ----
    {
        float* og = out + ((size_t)h * LL + (size_t)m * 64) * DD;
        const float inv0 = 1.0f / lrow0, inv1 = 1.0f / lrow1;
        const int r0 = 16 * w + g;
#pragma unroll
        for (int nt = 0; nt < 8; ++nt) {
            *(float2*)(og + (size_t)r0 * DD + 8 * nt + 2 * t4) =
                make_float2(O[nt][0] * inv0, O[nt][1] * inv0);
            *(float2*)(og + (size_t)(r0 + 8) * DD + 8 * nt + 2 * t4) =
                make_float2(O[nt][2] * inv1, O[nt][3] * inv1);
        }
    }
}

extern "C" void kernel_launch(void* const* d_in, const int* in_sizes, int n_in,
                              void* d_out, int out_size) {
    const float* q = (const float*)d_in[0];
    const float* k = (const float*)d_in[1];
    const float* v = (const float*)d_in[2];
    float* out = (float*)d_out;

    cudaFuncSetAttribute(attn_kernel, cudaFuncAttributeMaxDynamicSharedMemorySize, SMEM_BYTES);

    kmean1_kernel<<<dim3(HH, 32), 256>>>(k);
    kmean2_kernel<<<HH, 64>>>();
    pool_kernel<<<dim3(MB, HH, 2), 64>>>(q, k);
    lut_kernel<<<dim3(MB / 8, HH), 128>>>();
    attn_kernel<<<dim3(MB, HH), 256, SMEM_BYTES>>>(q, k, v, out);
}